// round 1
// baseline (speedup 1.0000x reference)
#include <cuda_runtime.h>

// ---------------- scratch (device globals: allocation-free) ----------------
__device__ float g_pool1[512 * 32 * 26 * 26];   // conv1+pool output, 44.3 MB
__device__ float g_pool2[512 * 64 * 12 * 12];   // conv2+pool output, 18.9 MB
__device__ float g_fc1part[32 * 512 * 128];     // fc1 split-K partials, 8.4 MB

// ============================================================================
// K1: conv1 (1->32, 3x3) + relu + 2x2 maxpool, fused.
// grid = 512 (one block per image), block = 676 = 26x26 pooled pixels.
// Whole 54x54 image staged in smem; each thread keeps its 4x4 input patch in
// registers and loops over the 32 output channels (weights broadcast from smem).
// ============================================================================
__global__ void __launch_bounds__(676) conv1_relu_pool(
    const float* __restrict__ x,
    const float* __restrict__ w,
    const float* __restrict__ bias)
{
    __shared__ float s_img[54 * 54];
    __shared__ float s_w[32 * 9];
    __shared__ float s_b[32];

    const int b   = blockIdx.x;
    const int tid = threadIdx.x;

    const float* xb = x + b * 54 * 54;
    for (int i = tid; i < 54 * 54; i += 676) s_img[i] = xb[i];
    for (int i = tid; i < 32 * 9;  i += 676) s_w[i]   = w[i];
    if (tid < 32) s_b[tid] = bias[tid];
    __syncthreads();

    const int ph = tid / 26;
    const int pw = tid % 26;

    float in[4][4];
#pragma unroll
    for (int r = 0; r < 4; r++)
#pragma unroll
        for (int c = 0; c < 4; c++)
            in[r][c] = s_img[(2 * ph + r) * 54 + 2 * pw + c];

    float* outp = g_pool1 + (b * 32) * 26 * 26 + ph * 26 + pw;

#pragma unroll 4
    for (int oc = 0; oc < 32; oc++) {
        const float* wp = &s_w[oc * 9];
        float v00 = 0.f, v01 = 0.f, v10 = 0.f, v11 = 0.f;
#pragma unroll
        for (int i = 0; i < 3; i++)
#pragma unroll
            for (int j = 0; j < 3; j++) {
                const float wv = wp[i * 3 + j];
                v00 = fmaf(in[i][j],         wv, v00);
                v01 = fmaf(in[i][j + 1],     wv, v01);
                v10 = fmaf(in[i + 1][j],     wv, v10);
                v11 = fmaf(in[i + 1][j + 1], wv, v11);
            }
        const float m = fmaxf(fmaxf(v00, v01), fmaxf(v10, v11)) + s_b[oc];
        outp[oc * 26 * 26] = fmaxf(m, 0.0f);
    }
}

// ============================================================================
// K2: conv2 (32->64, 3x3) + relu + 2x2 maxpool, fused.  Dominant kernel.
// grid = (512 images, 2 row-halves), block = 576 = 8 oc-groups x 72 pooled pos.
// Input slice (32 x 14 x 26) + ALL weights (padded to 12 floats per (oc,ic)
// for aligned float4 broadcast loads) staged in dynamic smem (141.5 KB).
// Each thread: 8 output channels x 1 pooled position -> 32 fp32 accumulators,
// 288 FMA per ic iteration vs ~28 LDS-cycles (weights are warp-broadcast).
// ============================================================================
__global__ void __launch_bounds__(576, 1) conv2_relu_pool(
    const float* __restrict__ w,
    const float* __restrict__ bias)
{
    extern __shared__ float sm[];
    float* s_in = sm;                     // 32*14*26 = 11648 floats
    float* s_w  = sm + 32 * 14 * 26;      // 64*32*12 = 24576 floats

    const int b    = blockIdx.x;
    const int half = blockIdx.y;          // pooled rows [half*6, half*6+6)
    const int tid  = threadIdx.x;

    // Stage input rows [12*half, 12*half+14) of the 26-row image, all 32 ic.
    const float* gin = g_pool1 + b * 32 * 26 * 26;
    for (int i = tid; i < 32 * 14 * 26; i += 576) {
        const int c  = i % 26;
        const int t  = i / 26;
        const int lr = t % 14;
        const int ic = t / 14;
        s_in[i] = gin[(ic * 26 + half * 12 + lr) * 26 + c];
    }
    // Stage weights, padded 9 -> 12 so each (oc,ic) filter is 16B-aligned.
    for (int i = tid; i < 64 * 32 * 9; i += 576) {
        const int k  = i % 9;
        const int oi = i / 9;
        s_w[oi * 12 + k] = w[i];
    }
    __syncthreads();

    const int ocg = tid / 72;             // 0..7 -> 8 output channels each
    const int pos = tid % 72;
    const int phl = pos / 12;             // 0..5 local pooled row
    const int pw  = pos % 12;

    float acc[8][4];
#pragma unroll
    for (int o = 0; o < 8; o++)
#pragma unroll
        for (int q = 0; q < 4; q++) acc[o][q] = 0.f;

#pragma unroll 1
    for (int ic = 0; ic < 32; ic++) {
        float in[4][4];
        const float* ip = &s_in[(ic * 14 + 2 * phl) * 26 + 2 * pw];
#pragma unroll
        for (int r = 0; r < 4; r++)
#pragma unroll
            for (int c = 0; c < 4; c++)
                in[r][c] = ip[r * 26 + c];

#pragma unroll
        for (int o = 0; o < 8; o++) {
            const int oc = ocg * 8 + o;
            const float4* wp = (const float4*)&s_w[(oc * 32 + ic) * 12];
            const float4 wa = wp[0];
            const float4 wb = wp[1];
            const float  w8 = s_w[(oc * 32 + ic) * 12 + 8];
            const float wv[9] = {wa.x, wa.y, wa.z, wa.w, wb.x, wb.y, wb.z, wb.w, w8};
#pragma unroll
            for (int i = 0; i < 3; i++)
#pragma unroll
                for (int j = 0; j < 3; j++) {
                    const float t = wv[i * 3 + j];
                    acc[o][0] = fmaf(in[i][j],         t, acc[o][0]);
                    acc[o][1] = fmaf(in[i][j + 1],     t, acc[o][1]);
                    acc[o][2] = fmaf(in[i + 1][j],     t, acc[o][2]);
                    acc[o][3] = fmaf(in[i + 1][j + 1], t, acc[o][3]);
                }
        }
    }

    const int ph = half * 6 + phl;
#pragma unroll
    for (int o = 0; o < 8; o++) {
        const int oc = ocg * 8 + o;
        const float m = fmaxf(fmaxf(acc[o][0], acc[o][1]),
                              fmaxf(acc[o][2], acc[o][3])) + __ldg(&bias[oc]);
        g_pool2[((b * 64 + oc) * 12 + ph) * 12 + pw] = fmaxf(m, 0.0f);
    }
}

// ============================================================================
// K3: fc1 as split-K SGEMM.  C[512,128] = A[512,9216] * W^T, K split 32 ways.
// grid = (8 M-tiles of 64, 32 K-chunks of 288), block = 256 (16x16 threads,
// each 4x8 register tile).  Partials -> g_fc1part.
// ============================================================================
__global__ void __launch_bounds__(256) fc1_splitk(const float* __restrict__ wfc1)
{
    __shared__ float sA[32][65];    // [k][m], padded
    __shared__ float sB[32][129];   // [k][n], padded

    const int mt  = blockIdx.x;     // 0..7
    const int ks  = blockIdx.y;     // 0..31
    const int tid = threadIdx.x;
    const int m0  = mt * 64;
    const int k0  = ks * 288;
    const int tx  = tid % 16;       // n
    const int ty  = tid / 16;       // m

    float acc[4][8];
#pragma unroll
    for (int i = 0; i < 4; i++)
#pragma unroll
        for (int j = 0; j < 8; j++) acc[i][j] = 0.f;

    const float* A = g_pool2;       // [512][9216], flatten matches reshape

    for (int kk = 0; kk < 288; kk += 32) {
        for (int i = tid; i < 64 * 32; i += 256) {
            const int m = i / 32, k = i % 32;
            sA[k][m] = A[(m0 + m) * 9216 + k0 + kk + k];
        }
        for (int i = tid; i < 128 * 32; i += 256) {
            const int n = i / 32, k = i % 32;
            sB[k][n] = wfc1[n * 9216 + k0 + kk + k];
        }
        __syncthreads();
#pragma unroll 8
        for (int k = 0; k < 32; k++) {
            float a[4], bv[8];
#pragma unroll
            for (int i = 0; i < 4; i++) a[i] = sA[k][ty * 4 + i];
#pragma unroll
            for (int j = 0; j < 8; j++) bv[j] = sB[k][tx * 8 + j];
#pragma unroll
            for (int i = 0; i < 4; i++)
#pragma unroll
                for (int j = 0; j < 8; j++)
                    acc[i][j] = fmaf(a[i], bv[j], acc[i][j]);
        }
        __syncthreads();
    }

    float* P = g_fc1part + (ks * 512 + m0 + ty * 4) * 128 + tx * 8;
#pragma unroll
    for (int i = 0; i < 4; i++)
#pragma unroll
        for (int j = 0; j < 8; j++)
            P[i * 128 + j] = acc[i][j];
}

// ============================================================================
// K4: reduce split-K partials + bias + relu, then the tiny fc2 (128->10).
// grid = 512 (one block per batch row), block = 128.
// ============================================================================
__global__ void __launch_bounds__(128) fc_tail(
    const float* __restrict__ b1,
    const float* __restrict__ w2,
    const float* __restrict__ b2,
    float* __restrict__ out)
{
    __shared__ float s_h[128];
    const int b   = blockIdx.x;
    const int tid = threadIdx.x;

    float s = 0.f;
#pragma unroll
    for (int ks = 0; ks < 32; ks++)
        s += g_fc1part[(ks * 512 + b) * 128 + tid];
    s_h[tid] = fmaxf(s + b1[tid], 0.0f);
    __syncthreads();

    if (tid < 10) {
        float acc = b2[tid];
        const float* w = w2 + tid * 128;
#pragma unroll 8
        for (int k = 0; k < 128; k++)
            acc = fmaf(s_h[k], w[k], acc);
        out[b * 10 + tid] = acc;
    }
}

// ============================================================================
extern "C" void kernel_launch(void* const* d_in, const int* in_sizes, int n_in,
                              void* d_out, int out_size)
{
    const float* x      = (const float*)d_in[0];
    const float* c1w    = (const float*)d_in[1];
    const float* c1b    = (const float*)d_in[2];
    const float* c2w    = (const float*)d_in[3];
    const float* c2b    = (const float*)d_in[4];
    const float* f1w    = (const float*)d_in[5];
    const float* f1b    = (const float*)d_in[6];
    const float* f2w    = (const float*)d_in[7];
    const float* f2b    = (const float*)d_in[8];
    float* out          = (float*)d_out;

    const int smem2 = (32 * 14 * 26 + 64 * 32 * 12) * (int)sizeof(float); // 144896 B
    cudaFuncSetAttribute(conv2_relu_pool,
                         cudaFuncAttributeMaxDynamicSharedMemorySize, smem2);

    conv1_relu_pool<<<512, 676>>>(x, c1w, c1b);

    dim3 g2(512, 2);
    conv2_relu_pool<<<g2, 576, smem2>>>(c2w, c2b);

    dim3 g3(8, 32);
    fc1_splitk<<<g3, 256>>>(f1w);

    fc_tail<<<512, 128>>>(f1b, f2w, f2b, out);
}

// round 3
// speedup vs baseline: 1.3404x; 1.3404x over previous
#include <cuda_runtime.h>
#include <cstdint>

// ---------------- scratch (device globals: allocation-free) ----------------
__device__ float g_pool1[512 * 26 * 26 * 32];   // conv1 out, NHWC, tf32-rounded
__device__ float g_pool2[512 * 144 * 64];       // conv2 out, NHWC [b][p][oc], tf32
__device__ float g_fc1part[32 * 512 * 128];     // fc1 split-K partials

__device__ __forceinline__ float to_tf32(float x) {
    float r;
    asm("cvt.rna.tf32.f32 %0, %1;" : "=f"(r) : "f"(x));
    return r;
}
__device__ __forceinline__ uint32_t f2u(float x) { return __float_as_uint(x); }

// Legacy tensor-core MMA: m16n8k8 tf32, fp32 accum (baseline PTX, sm_80+).
__device__ __forceinline__ void mma_tf32(float c[4],
                                         uint32_t a0, uint32_t a1,
                                         uint32_t a2, uint32_t a3,
                                         uint32_t b0, uint32_t b1) {
    asm volatile(
        "mma.sync.aligned.m16n8k8.row.col.f32.tf32.tf32.f32 "
        "{%0,%1,%2,%3}, {%4,%5,%6,%7}, {%8,%9}, {%0,%1,%2,%3};"
        : "+f"(c[0]), "+f"(c[1]), "+f"(c[2]), "+f"(c[3])
        : "r"(a0), "r"(a1), "r"(a2), "r"(a3), "r"(b0), "r"(b1));
}

// ============================================================================
// K1: conv1 (1->32, 3x3) + relu + 2x2 maxpool, fused, fp32.
// Writes NHWC (32 ch contiguous per pixel), tf32-rounded for conv2's MMA.
// ============================================================================
__global__ void __launch_bounds__(676) conv1_relu_pool(
    const float* __restrict__ x,
    const float* __restrict__ w,
    const float* __restrict__ bias)
{
    __shared__ float s_img[54 * 54];
    __shared__ float s_w[32 * 9];
    __shared__ float s_b[32];

    const int b   = blockIdx.x;
    const int tid = threadIdx.x;

    const float* xb = x + b * 54 * 54;
    for (int i = tid; i < 54 * 54; i += 676) s_img[i] = xb[i];
    for (int i = tid; i < 32 * 9;  i += 676) s_w[i]   = w[i];
    if (tid < 32) s_b[tid] = bias[tid];
    __syncthreads();

    const int ph = tid / 26;
    const int pw = tid % 26;

    float in[4][4];
#pragma unroll
    for (int r = 0; r < 4; r++)
#pragma unroll
        for (int c = 0; c < 4; c++)
            in[r][c] = s_img[(2 * ph + r) * 54 + 2 * pw + c];

    float* outp = g_pool1 + ((b * 26 + ph) * 26 + pw) * 32;   // NHWC

#pragma unroll 4
    for (int oc = 0; oc < 32; oc++) {
        const float* wp = &s_w[oc * 9];
        float v00 = 0.f, v01 = 0.f, v10 = 0.f, v11 = 0.f;
#pragma unroll
        for (int i = 0; i < 3; i++)
#pragma unroll
            for (int j = 0; j < 3; j++) {
                const float wv = wp[i * 3 + j];
                v00 = fmaf(in[i][j],         wv, v00);
                v01 = fmaf(in[i][j + 1],     wv, v01);
                v10 = fmaf(in[i + 1][j],     wv, v10);
                v11 = fmaf(in[i + 1][j + 1], wv, v11);
            }
        const float m = fmaxf(fmaxf(v00, v01), fmaxf(v10, v11)) + s_b[oc];
        outp[oc] = to_tf32(fmaxf(m, 0.0f));
    }
}

// ============================================================================
// K2: conv2 (32->64, 3x3) + relu + 2x2 maxpool via tf32 mma.sync.
// One CTA = one image, 8 warps. GEMM view: M = 640 pixel rows (26-grid, rows
// >= 624 are garbage, discarded), N = 64 oc, K = 9 shifts x 32 ic.
// Warp w owns m16-tiles [5w, 5w+5) x all of N -> acc[5][8][4] = 160 regs.
// Shift (di,dj) = A-row offset di*26+dj into the same staged image.
// XOR swizzles make all fragment LDS conflict-free. One epilogue phase after
// all MMAs lets s_epi alias the A/B staging buffers.
// ============================================================================
__global__ void __launch_bounds__(256, 1) conv2_tc(
    const float* __restrict__ w,
    const float* __restrict__ bias)
{
    extern __shared__ float sm[];
    float* s_a   = sm;              // 704 rows x 32 (90112 B), swizzled
    float* s_b   = sm + 704 * 32;   // 9 x 32k x 64n (73728 B), swizzled
    float* s_epi = sm;              // 24*24*64 floats (147456 B), reused
    __shared__ float s_bias[64];

    const int b    = blockIdx.x;
    const int tid  = threadIdx.x;
    const int wid  = tid >> 5;
    const int lane = tid & 31;
    const int g    = lane >> 2;     // groupID
    const int tig  = lane & 3;      // threadID_in_group

    if (tid < 64) s_bias[tid] = bias[tid];

    // Stage A (swizzle: col ^= (row&7)*4). Rows 676..703 zero.
    const float* gin = g_pool1 + b * (26 * 26 * 32);
    for (int i = tid; i < 676 * 32; i += 256) {
        const int m = i >> 5, ic = i & 31;
        s_a[(m << 5) + (ic ^ ((m & 7) << 2))] = gin[i];
    }
    for (int i = 676 * 32 + tid; i < 704 * 32; i += 256) {
        const int m = i >> 5, ic = i & 31;
        s_a[(m << 5) + (ic ^ ((m & 7) << 2))] = 0.0f;
    }
    // Stage B: s_b[s][k][n ^ (k&3)*8] = tf32(w[n][k][s])
    for (int i = tid; i < 9 * 32 * 64; i += 256) {
        const int n = i & 63;
        const int k = (i >> 6) & 31;
        const int s = i >> 11;
        s_b[((s * 32 + k) << 6) + (n ^ ((k & 3) << 3))] =
            to_tf32(w[(n * 32 + k) * 9 + s]);
    }
    __syncthreads();

    float acc[5][8][4];
#pragma unroll
    for (int i = 0; i < 5; i++)
#pragma unroll
        for (int n = 0; n < 8; n++)
#pragma unroll
            for (int q = 0; q < 4; q++) acc[i][n][q] = 0.0f;

    const int mbase = wid * 80;     // 5 m16-tiles per warp

#pragma unroll 1
    for (int s = 0; s < 9; s++) {
        const int roff = (s / 3) * 26 + (s % 3);
        const int sb   = s * 32;
#pragma unroll
        for (int ks = 0; ks < 4; ks++) {
            const int kb = ks * 8;
            const int c0 = kb + tig, c1 = kb + tig + 4;

            uint32_t a[5][4];
#pragma unroll
            for (int i = 0; i < 5; i++) {
                const int r0 = mbase + i * 16 + g + roff;
                const int r1 = r0 + 8;
                a[i][0] = f2u(s_a[(r0 << 5) + ((c0 & 31) ^ ((r0 & 7) << 2))]);
                a[i][1] = f2u(s_a[(r1 << 5) + ((c0 & 31) ^ ((r1 & 7) << 2))]);
                a[i][2] = f2u(s_a[(r0 << 5) + ((c1 & 31) ^ ((r0 & 7) << 2))]);
                a[i][3] = f2u(s_a[(r1 << 5) + ((c1 & 31) ^ ((r1 & 7) << 2))]);
            }
#pragma unroll
            for (int n = 0; n < 8; n++) {
                const int nn = n * 8 + g;
                const uint32_t b0 =
                    f2u(s_b[((sb + c0) << 6) + (nn ^ ((tig & 3) << 3))]);
                const uint32_t b1 =
                    f2u(s_b[((sb + c1) << 6) + (nn ^ ((tig & 3) << 3))]);
#pragma unroll
                for (int i = 0; i < 5; i++)
                    mma_tf32(acc[i][n], a[i][0], a[i][1], a[i][2], a[i][3], b0, b1);
            }
        }
    }
    __syncthreads();   // all MMA results in regs; smem now dead -> reuse

    // Epilogue: scatter bias-added conv outputs to pixel-major s_epi.
#pragma unroll
    for (int i = 0; i < 5; i++) {
        const int r0 = mbase + i * 16 + g;
        const int r1 = r0 + 8;
        const int h0 = r0 / 26, w0 = r0 % 26;
        const int h1 = r1 / 26, w1 = r1 % 26;
#pragma unroll
        for (int n = 0; n < 8; n++) {
            const int col0 = n * 8 + tig * 2;
            if (h0 < 24 && w0 < 24) {
                float* e = s_epi + (h0 * 24 + w0) * 64;
                e[col0]     = acc[i][n][0] + s_bias[col0];
                e[col0 + 1] = acc[i][n][1] + s_bias[col0 + 1];
            }
            if (h1 < 24 && w1 < 24) {
                float* e = s_epi + (h1 * 24 + w1) * 64;
                e[col0]     = acc[i][n][2] + s_bias[col0];
                e[col0 + 1] = acc[i][n][3] + s_bias[col0 + 1];
            }
        }
    }
    __syncthreads();

    // 2x2 maxpool + relu -> gmem NHWC [b][144][64], tf32-rounded for fc1 MMA.
    float* outp = g_pool2 + b * (144 * 64);
    for (int j = tid; j < 144 * 64; j += 256) {
        const int oc = j & 63;
        const int p  = j >> 6;
        const int ph = p / 12, pw = p % 12;
        const float* e = s_epi + ((2 * ph) * 24 + 2 * pw) * 64 + oc;
        const float v = fmaxf(fmaxf(e[0], e[64]),
                              fmaxf(e[24 * 64], e[25 * 64]));
        outp[j] = to_tf32(fmaxf(v, 0.0f));
    }
}

// ============================================================================
// K3: fc1 split-K via tf32 mma.sync.  C[512,128] = A[512,9216] * W^T.
// grid = (8 m-tiles of 64, 32 k-chunks of 288), 256 thr = 8 warps.
// Warp (mi, nh): m16-tile mi, n-half nh (64 cols = 8 n8-tiles) -> 32 accum.
// Logical K = oc*144 + pixel (reference NCHW flatten); A gathered from NHWC.
// ============================================================================
__global__ void __launch_bounds__(256) fc1_tc(const float* __restrict__ wfc1)
{
    __shared__ float sA[64 * 32];
    __shared__ float sB[32 * 128];

    const int mt   = blockIdx.x;    // 0..7
    const int ks   = blockIdx.y;    // 0..31
    const int tid  = threadIdx.x;
    const int wid  = tid >> 5;
    const int lane = tid & 31;
    const int g    = lane >> 2;
    const int tig  = lane & 3;
    const int m0   = mt * 64;
    const int k0   = ks * 288;
    const int mi   = wid & 3;       // m16-tile within the 64-row block
    const int nh   = wid >> 2;      // n-half (0 or 1)

    float acc[8][4];
#pragma unroll
    for (int n = 0; n < 8; n++)
#pragma unroll
        for (int q = 0; q < 4; q++) acc[n][q] = 0.0f;

#pragma unroll 1
    for (int kk = 0; kk < 288; kk += 32) {
        __syncthreads();
        for (int i = tid; i < 64 * 32; i += 256) {
            const int m = i >> 5, k = i & 31;
            const int klog = k0 + kk + k;
            sA[(m << 5) + (k ^ ((m & 7) << 2))] =
                g_pool2[((m0 + m) * 144 + (klog % 144)) * 64 + (klog / 144)];
        }
        for (int i = tid; i < 32 * 128; i += 256) {
            const int k = i >> 7, n = i & 127;
            sB[(k << 7) + (n ^ ((k & 3) << 3))] =
                to_tf32(wfc1[n * 9216 + k0 + kk + k]);
        }
        __syncthreads();

#pragma unroll
        for (int kstep = 0; kstep < 4; kstep++) {
            const int kb = kstep * 8;
            const int r0 = mi * 16 + g, r1 = r0 + 8;
            const int c0 = kb + tig,   c1 = c0 + 4;
            const uint32_t a0 = f2u(sA[(r0 << 5) + ((c0 & 31) ^ ((r0 & 7) << 2))]);
            const uint32_t a1 = f2u(sA[(r1 << 5) + ((c0 & 31) ^ ((r1 & 7) << 2))]);
            const uint32_t a2 = f2u(sA[(r0 << 5) + ((c1 & 31) ^ ((r0 & 7) << 2))]);
            const uint32_t a3 = f2u(sA[(r1 << 5) + ((c1 & 31) ^ ((r1 & 7) << 2))]);
#pragma unroll
            for (int n = 0; n < 8; n++) {
                const int nn = nh * 64 + n * 8 + g;
                const uint32_t b0 = f2u(sB[((kb + tig)     << 7) + (nn ^ ((tig & 3) << 3))]);
                const uint32_t b1 = f2u(sB[((kb + tig + 4) << 7) + (nn ^ ((tig & 3) << 3))]);
                mma_tf32(acc[n], a0, a1, a2, a3, b0, b1);
            }
        }
    }

    float* P = g_fc1part + (ks * 512 + m0) * 128;
    const int r0 = mi * 16 + g;
#pragma unroll
    for (int n = 0; n < 8; n++) {
        const int c0 = nh * 64 + n * 8 + tig * 2;
        P[r0 * 128 + c0]           = acc[n][0];
        P[r0 * 128 + c0 + 1]       = acc[n][1];
        P[(r0 + 8) * 128 + c0]     = acc[n][2];
        P[(r0 + 8) * 128 + c0 + 1] = acc[n][3];
    }
}

// ============================================================================
// K4: reduce split-K partials + bias + relu + fc2 (128->10).
// ============================================================================
__global__ void __launch_bounds__(128) fc_tail(
    const float* __restrict__ b1,
    const float* __restrict__ w2,
    const float* __restrict__ b2,
    float* __restrict__ out)
{
    __shared__ float s_h[128];
    const int b   = blockIdx.x;
    const int tid = threadIdx.x;

    float s = 0.f;
#pragma unroll
    for (int ks = 0; ks < 32; ks++)
        s += g_fc1part[(ks * 512 + b) * 128 + tid];
    s_h[tid] = fmaxf(s + b1[tid], 0.0f);
    __syncthreads();

    if (tid < 10) {
        float acc = b2[tid];
        const float* w = w2 + tid * 128;
#pragma unroll 8
        for (int k = 0; k < 128; k++)
            acc = fmaf(s_h[k], w[k], acc);
        out[b * 10 + tid] = acc;
    }
}

// ============================================================================
extern "C" void kernel_launch(void* const* d_in, const int* in_sizes, int n_in,
                              void* d_out, int out_size)
{
    const float* x   = (const float*)d_in[0];
    const float* c1w = (const float*)d_in[1];
    const float* c1b = (const float*)d_in[2];
    const float* c2w = (const float*)d_in[3];
    const float* c2b = (const float*)d_in[4];
    const float* f1w = (const float*)d_in[5];
    const float* f1b = (const float*)d_in[6];
    const float* f2w = (const float*)d_in[7];
    const float* f2b = (const float*)d_in[8];
    float* out       = (float*)d_out;

    const int smem2 = (704 * 32 + 9 * 32 * 64) * (int)sizeof(float);  // 163840 B
    cudaFuncSetAttribute(conv2_tc,
                         cudaFuncAttributeMaxDynamicSharedMemorySize, smem2);

    conv1_relu_pool<<<512, 676>>>(x, c1w, c1b);
    conv2_tc<<<512, 256, smem2>>>(c2w, c2b);

    dim3 g3(8, 32);
    fc1_tc<<<g3, 256>>>(f1w);

    fc_tail<<<512, 128>>>(f1b, f2w, f2b, out);
}

// round 4
// speedup vs baseline: 2.0969x; 1.5644x over previous
#include <cuda_runtime.h>
#include <cstdint>

// ---------------- scratch (device globals: allocation-free) ----------------
__device__ float g_pool2[512 * 64 * 144];       // conv2 out, NCHW flat [b][9216]
__device__ float g_fc1part[32 * 512 * 128];     // fc1 split-K partials

__device__ __forceinline__ float to_tf32(float x) {
    float r;
    asm("cvt.rna.tf32.f32 %0, %1;" : "=f"(r) : "f"(x));
    return r;
}
__device__ __forceinline__ uint32_t f2u(float x) { return __float_as_uint(x); }

// Legacy tensor-core MMA: m16n8k8 tf32, fp32 accum (baseline PTX, sm_80+).
__device__ __forceinline__ void mma_tf32(float c[4],
                                         uint32_t a0, uint32_t a1,
                                         uint32_t a2, uint32_t a3,
                                         uint32_t b0, uint32_t b1) {
    asm volatile(
        "mma.sync.aligned.m16n8k8.row.col.f32.tf32.tf32.f32 "
        "{%0,%1,%2,%3}, {%4,%5,%6,%7}, {%8,%9}, {%0,%1,%2,%3};"
        : "+f"(c[0]), "+f"(c[1]), "+f"(c[2]), "+f"(c[3])
        : "r"(a0), "r"(a1), "r"(a2), "r"(a3), "r"(b0), "r"(b1));
}

// ============================================================================
// K1 (fused): conv1+relu+pool (fp32, in-smem) -> conv2 via tf32 mma.sync
//             -> bias+relu+pool -> NCHW gmem.
// One CTA = one image, 8 warps, 256 threads.
// conv2 GEMM view: M = 640 pixel rows over the 26-grid (cols 24,25 garbage,
// dropped in epilogue), N = 64 oc, K = 9 shifts x 32 ic; shift (di,dj) is an
// A-row offset of di*26+dj into the SAME staged conv1 output.
// ============================================================================
__global__ void __launch_bounds__(256, 1) convs_fused(
    const float* __restrict__ x,
    const float* __restrict__ w1,
    const float* __restrict__ b1,
    const float* __restrict__ w2,
    const float* __restrict__ b2)
{
    extern __shared__ float sm[];
    float* s_a   = sm;              // 704 rows x 32 (90112 B), XOR-swizzled
    float* s_b   = sm + 704 * 32;   // 9 x 32k x 64n (73728 B), XOR-swizzled
    float* s_img = sm + 704 * 32 + 9 * 2048;  // 54*54 (11664 B)
    float* s_epi = sm;              // 64 oc x 576 pix (147456 B), reused
    __shared__ float s_w1[32 * 9];
    __shared__ float s_b1[32];
    __shared__ float s_bias[64];

    const int b    = blockIdx.x;
    const int tid  = threadIdx.x;
    const int wid  = tid >> 5;
    const int lane = tid & 31;
    const int g    = lane >> 2;     // groupID
    const int tig  = lane & 3;      // threadID_in_group

    // ---- stage raw image + all weights (all coalesced gmem reads) ----
    const float* xb = x + b * 54 * 54;
    for (int i = tid; i < 54 * 54; i += 256) s_img[i] = xb[i];
    for (int i = tid; i < 32 * 9; i += 256) s_w1[i] = w1[i];
    if (tid < 32) s_b1[tid] = b1[tid];
    if (tid < 64) s_bias[tid] = b2[tid];
    // conv2 weights: i enumerates (n,k,s) with s fastest -> w2[i] coalesced.
    for (int i = tid; i < 64 * 32 * 9; i += 256) {
        const int n = i / 288;
        const int r = i % 288;
        const int k = r / 9;
        const int s = r % 9;
        s_b[((s * 32 + k) << 6) + (n ^ ((k & 3) << 3))] = to_tf32(w2[i]);
    }
    // zero-pad A rows [676, 704)
    for (int i = 676 * 32 + tid; i < 704 * 32; i += 256) {
        const int m = i >> 5, ic = i & 31;
        s_a[(m << 5) + (ic ^ ((m & 7) << 2))] = 0.0f;
    }
    __syncthreads();

    // ---- conv1 + relu + 2x2 pool (fp32) -> swizzled s_a rows ----
    for (int m = tid; m < 676; m += 256) {
        const int ph = m / 26, pw = m % 26;
        float in[4][4];
#pragma unroll
        for (int r = 0; r < 4; r++)
#pragma unroll
            for (int c = 0; c < 4; c++)
                in[r][c] = s_img[(2 * ph + r) * 54 + 2 * pw + c];
        float* arow = s_a + (m << 5);
        const uint32_t sw = (m & 7) << 2;
#pragma unroll 4
        for (int oc = 0; oc < 32; oc++) {
            const float* wp = &s_w1[oc * 9];
            float v00 = 0.f, v01 = 0.f, v10 = 0.f, v11 = 0.f;
#pragma unroll
            for (int i = 0; i < 3; i++)
#pragma unroll
                for (int j = 0; j < 3; j++) {
                    const float wv = wp[i * 3 + j];
                    v00 = fmaf(in[i][j],         wv, v00);
                    v01 = fmaf(in[i][j + 1],     wv, v01);
                    v10 = fmaf(in[i + 1][j],     wv, v10);
                    v11 = fmaf(in[i + 1][j + 1], wv, v11);
                }
            const float mx = fmaxf(fmaxf(v00, v01), fmaxf(v10, v11)) + s_b1[oc];
            arow[oc ^ sw] = to_tf32(fmaxf(mx, 0.0f));
        }
    }
    __syncthreads();

    // ---- conv2 mainloop: 9 shifts x 4 k-steps, acc[5][8][4] per thread ----
    float acc[5][8][4];
#pragma unroll
    for (int i = 0; i < 5; i++)
#pragma unroll
        for (int n = 0; n < 8; n++)
#pragma unroll
            for (int q = 0; q < 4; q++) acc[i][n][q] = 0.0f;

    const int mbase = wid * 80;     // 5 m16-tiles per warp

#pragma unroll 1
    for (int s = 0; s < 9; s++) {
        const int roff = (s / 3) * 26 + (s % 3);
        const int sb   = s * 32;
#pragma unroll
        for (int ks = 0; ks < 4; ks++) {
            const int kb = ks * 8;
            const int c0 = kb + tig, c1 = kb + tig + 4;

            uint32_t a[5][4];
#pragma unroll
            for (int i = 0; i < 5; i++) {
                const int r0 = mbase + i * 16 + g + roff;
                const int r1 = r0 + 8;
                a[i][0] = f2u(s_a[(r0 << 5) + ((c0 & 31) ^ ((r0 & 7) << 2))]);
                a[i][1] = f2u(s_a[(r1 << 5) + ((c0 & 31) ^ ((r1 & 7) << 2))]);
                a[i][2] = f2u(s_a[(r0 << 5) + ((c1 & 31) ^ ((r0 & 7) << 2))]);
                a[i][3] = f2u(s_a[(r1 << 5) + ((c1 & 31) ^ ((r1 & 7) << 2))]);
            }
#pragma unroll
            for (int n = 0; n < 8; n++) {
                const int nn = n * 8 + g;
                const uint32_t bb0 =
                    f2u(s_b[((sb + c0) << 6) + (nn ^ ((tig & 3) << 3))]);
                const uint32_t bb1 =
                    f2u(s_b[((sb + c1) << 6) + (nn ^ ((tig & 3) << 3))]);
#pragma unroll
                for (int i = 0; i < 5; i++)
                    mma_tf32(acc[i][n], a[i][0], a[i][1], a[i][2], a[i][3], bb0, bb1);
            }
        }
    }
    __syncthreads();   // MMA results in regs; staging smem dead -> reuse

    // ---- epilogue: scatter bias-added outputs to [oc][pix] smem ----
#pragma unroll
    for (int i = 0; i < 5; i++) {
        const int r0 = mbase + i * 16 + g;
        const int r1 = r0 + 8;
        const int h0 = r0 / 26, w0 = r0 % 26;
        const int h1 = r1 / 26, w1 = r1 % 26;
#pragma unroll
        for (int n = 0; n < 8; n++) {
            const int col0 = n * 8 + tig * 2;
            if (h0 < 24 && w0 < 24) {
                const int pix = h0 * 24 + w0;
                s_epi[col0 * 576 + pix]       = acc[i][n][0] + s_bias[col0];
                s_epi[(col0 + 1) * 576 + pix] = acc[i][n][1] + s_bias[col0 + 1];
            }
            if (h1 < 24 && w1 < 24) {
                const int pix = h1 * 24 + w1;
                s_epi[col0 * 576 + pix]       = acc[i][n][2] + s_bias[col0];
                s_epi[(col0 + 1) * 576 + pix] = acc[i][n][3] + s_bias[col0 + 1];
            }
        }
    }
    __syncthreads();

    // ---- 2x2 maxpool + relu -> gmem NCHW flat [b][oc*144+p] (coalesced) ----
    float* outp = g_pool2 + b * 9216;
    for (int j = tid; j < 9216; j += 256) {
        const int oc = j / 144;
        const int p  = j % 144;
        const int ph = p / 12, pw = p % 12;
        const float* e = s_epi + oc * 576 + (2 * ph) * 24 + 2 * pw;
        const float v = fmaxf(fmaxf(e[0], e[1]), fmaxf(e[24], e[25]));
        outp[j] = to_tf32(fmaxf(v, 0.0f));
    }
}

// ============================================================================
// K2: fc1 split-K via tf32 mma.sync.  C[512,128] = A[512,9216] * W^T.
// A now NCHW-flat -> contiguous, coalesced loads. B staged n-major with
// pad 36 (conflict-free stores and fragment reads, coalesced gmem).
// grid = (8 m-tiles of 64, 32 k-chunks of 288), 256 thr = 8 warps.
// ============================================================================
__global__ void __launch_bounds__(256) fc1_tc(const float* __restrict__ wfc1)
{
    __shared__ float sA[64 * 32];     // swizzled [m][k]
    __shared__ float sB[128 * 36];    // n-major, pad 36

    const int mt   = blockIdx.x;    // 0..7
    const int ks   = blockIdx.y;    // 0..31
    const int tid  = threadIdx.x;
    const int wid  = tid >> 5;
    const int lane = tid & 31;
    const int g    = lane >> 2;
    const int tig  = lane & 3;
    const int m0   = mt * 64;
    const int k0   = ks * 288;
    const int mi   = wid & 3;       // m16-tile within the 64-row block
    const int nh   = wid >> 2;      // n-half (0 or 1)

    float acc[8][4];
#pragma unroll
    for (int n = 0; n < 8; n++)
#pragma unroll
        for (int q = 0; q < 4; q++) acc[n][q] = 0.0f;

#pragma unroll 1
    for (int kk = 0; kk < 288; kk += 32) {
        __syncthreads();
        for (int i = tid; i < 64 * 32; i += 256) {
            const int m = i >> 5, k = i & 31;
            sA[(m << 5) + (k ^ ((m & 7) << 2))] =
                g_pool2[(m0 + m) * 9216 + k0 + kk + k];         // coalesced
        }
        for (int i = tid; i < 128 * 32; i += 256) {
            const int n = i >> 5, k = i & 31;
            sB[n * 36 + k] = to_tf32(wfc1[n * 9216 + k0 + kk + k]);  // coalesced
        }
        __syncthreads();

#pragma unroll
        for (int kstep = 0; kstep < 4; kstep++) {
            const int kb = kstep * 8;
            const int r0 = mi * 16 + g, r1 = r0 + 8;
            const int c0 = kb + tig,   c1 = c0 + 4;
            const uint32_t a0 = f2u(sA[(r0 << 5) + ((c0 & 31) ^ ((r0 & 7) << 2))]);
            const uint32_t a1 = f2u(sA[(r1 << 5) + ((c0 & 31) ^ ((r1 & 7) << 2))]);
            const uint32_t a2 = f2u(sA[(r0 << 5) + ((c1 & 31) ^ ((r0 & 7) << 2))]);
            const uint32_t a3 = f2u(sA[(r1 << 5) + ((c1 & 31) ^ ((r1 & 7) << 2))]);
#pragma unroll
            for (int n = 0; n < 8; n++) {
                const int nn = nh * 64 + n * 8 + g;
                const uint32_t bb0 = f2u(sB[nn * 36 + c0]);
                const uint32_t bb1 = f2u(sB[nn * 36 + c1]);
                mma_tf32(acc[n], a0, a1, a2, a3, bb0, bb1);
            }
        }
    }

    float* P = g_fc1part + (ks * 512 + m0) * 128;
    const int r0 = mi * 16 + g;
#pragma unroll
    for (int n = 0; n < 8; n++) {
        const int c0 = nh * 64 + n * 8 + tig * 2;
        P[r0 * 128 + c0]           = acc[n][0];
        P[r0 * 128 + c0 + 1]       = acc[n][1];
        P[(r0 + 8) * 128 + c0]     = acc[n][2];
        P[(r0 + 8) * 128 + c0 + 1] = acc[n][3];
    }
}

// ============================================================================
// K3: reduce split-K partials + bias + relu + fc2 (128->10).
// ============================================================================
__global__ void __launch_bounds__(128) fc_tail(
    const float* __restrict__ b1,
    const float* __restrict__ w2,
    const float* __restrict__ b2,
    float* __restrict__ out)
{
    __shared__ float s_h[128];
    const int b   = blockIdx.x;
    const int tid = threadIdx.x;

    float s = 0.f;
#pragma unroll
    for (int ks = 0; ks < 32; ks++)
        s += g_fc1part[(ks * 512 + b) * 128 + tid];
    s_h[tid] = fmaxf(s + b1[tid], 0.0f);
    __syncthreads();

    if (tid < 10) {
        float acc = b2[tid];
        const float* w = w2 + tid * 128;
#pragma unroll 8
        for (int k = 0; k < 128; k++)
            acc = fmaf(s_h[k], w[k], acc);
        out[b * 10 + tid] = acc;
    }
}

// ============================================================================
extern "C" void kernel_launch(void* const* d_in, const int* in_sizes, int n_in,
                              void* d_out, int out_size)
{
    const float* x   = (const float*)d_in[0];
    const float* c1w = (const float*)d_in[1];
    const float* c1b = (const float*)d_in[2];
    const float* c2w = (const float*)d_in[3];
    const float* c2b = (const float*)d_in[4];
    const float* f1w = (const float*)d_in[5];
    const float* f1b = (const float*)d_in[6];
    const float* f2w = (const float*)d_in[7];
    const float* f2b = (const float*)d_in[8];
    float* out       = (float*)d_out;

    // 704*32 A + 9*2048 B + 54*54 img = 43876 floats = 175504 B dynamic smem
    const int smem = (704 * 32 + 9 * 2048 + 54 * 54) * (int)sizeof(float);
    cudaFuncSetAttribute(convs_fused,
                         cudaFuncAttributeMaxDynamicSharedMemorySize, smem);

    convs_fused<<<512, 256, smem>>>(x, c1w, c1b, c2w, c2b);

    dim3 g2(8, 32);
    fc1_tc<<<g2, 256>>>(f1w);

    fc_tail<<<512, 128>>>(f1b, f2w, f2b, out);
}

// round 5
// speedup vs baseline: 2.1451x; 1.0230x over previous
#include <cuda_runtime.h>
#include <cstdint>

// ---------------- scratch (device globals: allocation-free) ----------------
__device__ float g_pool2[512 * 64 * 144];       // conv2 out, NCHW flat [b][9216]
__device__ float g_fc1part[32 * 512 * 128];     // fc1 split-K partials

__device__ __forceinline__ float to_tf32(float x) {
    float r;
    asm("cvt.rna.tf32.f32 %0, %1;" : "=f"(r) : "f"(x));
    return r;
}
__device__ __forceinline__ uint32_t f2u(float x) { return __float_as_uint(x); }
__device__ __forceinline__ uint32_t smem_u32(const void* p) {
    return (uint32_t)__cvta_generic_to_shared(p);
}

// Legacy tensor-core MMA: m16n8k8 tf32, fp32 accum (baseline PTX, sm_80+).
__device__ __forceinline__ void mma_tf32(float c[4],
                                         uint32_t a0, uint32_t a1,
                                         uint32_t a2, uint32_t a3,
                                         uint32_t b0, uint32_t b1) {
    asm volatile(
        "mma.sync.aligned.m16n8k8.row.col.f32.tf32.tf32.f32 "
        "{%0,%1,%2,%3}, {%4,%5,%6,%7}, {%8,%9}, {%0,%1,%2,%3};"
        : "+f"(c[0]), "+f"(c[1]), "+f"(c[2]), "+f"(c[3])
        : "r"(a0), "r"(a1), "r"(a2), "r"(a3), "r"(b0), "r"(b1));
}

// ldmatrix x4 (baseline PTX, sm_75+): 4 m8n8 b16 tiles = 16 rows x 16B.
__device__ __forceinline__ void ldmx4(uint32_t r[4], uint32_t addr) {
    asm volatile(
        "ldmatrix.sync.aligned.m8n8.x4.shared.b16 {%0,%1,%2,%3}, [%4];"
        : "=r"(r[0]), "=r"(r[1]), "=r"(r[2]), "=r"(r[3]) : "r"(addr));
}

// ============================================================================
// K1 (fused): conv1+relu+pool (fp32, in-smem) -> conv2 via tf32 mma.sync
//             -> bias+relu+pool -> NCHW gmem.
// One CTA = one image, 8 warps. conv2 GEMM: M = 640 pixel rows over the
// 26-grid (cols 24,25 garbage, dropped), N = 64 oc, K = 9 shifts x 32 ic.
// Mainloop operands via ldmatrix.x4 (1 LDSM per m16-tile / per 2 n8-tiles).
// Both A and B live in 128B rows with 16B-group XOR swizzle (g ^= row&7):
// every LDSM phase hits 8 distinct bank groups.
// ============================================================================
__global__ void __launch_bounds__(256, 1) convs_fused(
    const float* __restrict__ x,
    const float* __restrict__ w1,
    const float* __restrict__ b1,
    const float* __restrict__ w2,
    const float* __restrict__ b2)
{
    extern __shared__ float sm[];
    float* s_a   = sm;              // 704 rows x 32 floats (90112 B), swizzled
    float* s_b   = sm + 704 * 32;   // 9*64 rows x 32 floats (73728 B), n-major swizzled
    float* s_img = sm + 704 * 32 + 9 * 2048;  // 54*54 (11664 B)
    float* s_epi = sm;              // 64 oc x 576 pix (147456 B), reused
    __shared__ float s_w1[32 * 9];
    __shared__ float s_b1[32];
    __shared__ float s_bias[64];

    const int b    = blockIdx.x;
    const int tid  = threadIdx.x;
    const int wid  = tid >> 5;
    const int lane = tid & 31;
    const int g    = lane >> 2;     // groupID
    const int tig  = lane & 3;      // threadID_in_group

    // ---- stage raw image + all weights (coalesced gmem reads) ----
    const float* xb = x + b * 54 * 54;
    for (int i = tid; i < 54 * 54; i += 256) s_img[i] = xb[i];
    for (int i = tid; i < 32 * 9; i += 256) s_w1[i] = w1[i];
    if (tid < 32) s_b1[tid] = b1[tid];
    if (tid < 64) s_bias[tid] = b2[tid];
    // conv2 weights -> n-major rows: s_b[(s*64+n)][k], group-swizzled by n&7.
    for (int i = tid; i < 64 * 32 * 9; i += 256) {
        const int n = i / 288;
        const int r = i % 288;
        const int k = r / 9;
        const int s = r % 9;
        s_b[((s * 64 + n) << 5) + ((((k >> 2) ^ (n & 7)) << 2) | (k & 3))] =
            to_tf32(w2[i]);
    }
    // zero-pad A rows [676, 704)
    for (int i = 676 * 32 + tid; i < 704 * 32; i += 256) {
        const int m = i >> 5, ic = i & 31;
        s_a[(m << 5) + (ic ^ ((m & 7) << 2))] = 0.0f;
    }
    __syncthreads();

    // ---- conv1 + relu + 2x2 pool (fp32) -> swizzled s_a rows ----
    for (int m = tid; m < 676; m += 256) {
        const int ph = m / 26, pw = m % 26;
        float in[4][4];
#pragma unroll
        for (int r = 0; r < 4; r++)
#pragma unroll
            for (int c = 0; c < 4; c++)
                in[r][c] = s_img[(2 * ph + r) * 54 + 2 * pw + c];
        float* arow = s_a + (m << 5);
        const uint32_t sw = (m & 7) << 2;
#pragma unroll 4
        for (int oc = 0; oc < 32; oc++) {
            const float* wp = &s_w1[oc * 9];
            float v00 = 0.f, v01 = 0.f, v10 = 0.f, v11 = 0.f;
#pragma unroll
            for (int i = 0; i < 3; i++)
#pragma unroll
                for (int j = 0; j < 3; j++) {
                    const float wv = wp[i * 3 + j];
                    v00 = fmaf(in[i][j],         wv, v00);
                    v01 = fmaf(in[i][j + 1],     wv, v01);
                    v10 = fmaf(in[i + 1][j],     wv, v10);
                    v11 = fmaf(in[i + 1][j + 1], wv, v11);
                }
            const float mx = fmaxf(fmaxf(v00, v01), fmaxf(v10, v11)) + s_b1[oc];
            arow[oc ^ sw] = to_tf32(fmaxf(mx, 0.0f));
        }
    }
    __syncthreads();

    // ---- conv2 mainloop ----
    float acc[5][8][4];
#pragma unroll
    for (int i = 0; i < 5; i++)
#pragma unroll
        for (int n = 0; n < 8; n++)
#pragma unroll
            for (int q = 0; q < 4; q++) acc[i][n][q] = 0.0f;

    const int mbase = wid * 80;     // 5 m16-tiles per warp

    const uint32_t a_base = smem_u32(s_a);
    const uint32_t b_base = smem_u32(s_b);
    const int lrow = lane & 15;            // A local row within m16
    const int lhi  = lane >> 4;            // A col-group select (0/1)
    const int bnl  = (lane & 7) | (((lane >> 4) & 1) << 3);  // B local n row
    const int bch  = (lane >> 3) & 1;      // B chunk select (0/1)

#pragma unroll 1
    for (int s = 0; s < 9; s++) {
        const int roff = (s / 3) * 26 + (s % 3);
        const int arow = mbase + roff + lrow;
        const uint32_t a_row_addr = a_base + arow * 128;
        const int asw  = arow & 7;
        const uint32_t b_row_addr = b_base + (s * 64 + bnl) * 128;
        const int bsw  = bnl & 7;

#pragma unroll
        for (int ks = 0; ks < 4; ks++) {
            const uint32_t aaddr =
                a_row_addr + ((uint32_t)((((ks << 1) + lhi) ^ asw)) << 4);
            const uint32_t baddr =
                b_row_addr + ((uint32_t)((((ks << 1) + bch) ^ bsw)) << 4);

            uint32_t a[5][4];
#pragma unroll
            for (int i = 0; i < 5; i++) ldmx4(a[i], aaddr + i * 2048);
            uint32_t bf[4][4];
#pragma unroll
            for (int p = 0; p < 4; p++) ldmx4(bf[p], baddr + p * 2048);

#pragma unroll
            for (int n = 0; n < 8; n++) {
                const uint32_t b0 = bf[n >> 1][(n & 1) * 2];
                const uint32_t b1 = bf[n >> 1][(n & 1) * 2 + 1];
#pragma unroll
                for (int i = 0; i < 5; i++)
                    mma_tf32(acc[i][n], a[i][0], a[i][1], a[i][2], a[i][3], b0, b1);
            }
        }
    }
    __syncthreads();   // MMA results in regs; staging smem dead -> reuse

    // ---- epilogue: scatter bias-added outputs to [oc][pix] smem ----
#pragma unroll
    for (int i = 0; i < 5; i++) {
        const int r0 = mbase + i * 16 + g;
        const int r1 = r0 + 8;
        const int h0 = r0 / 26, w0 = r0 % 26;
        const int h1 = r1 / 26, w1 = r1 % 26;
#pragma unroll
        for (int n = 0; n < 8; n++) {
            const int col0 = n * 8 + tig * 2;
            if (h0 < 24 && w0 < 24) {
                const int pix = h0 * 24 + w0;
                s_epi[col0 * 576 + pix]       = acc[i][n][0] + s_bias[col0];
                s_epi[(col0 + 1) * 576 + pix] = acc[i][n][1] + s_bias[col0 + 1];
            }
            if (h1 < 24 && w1 < 24) {
                const int pix = h1 * 24 + w1;
                s_epi[col0 * 576 + pix]       = acc[i][n][2] + s_bias[col0];
                s_epi[(col0 + 1) * 576 + pix] = acc[i][n][3] + s_bias[col0 + 1];
            }
        }
    }
    __syncthreads();

    // ---- 2x2 maxpool + relu -> gmem NCHW flat [b][oc*144+p] (coalesced) ----
    float* outp = g_pool2 + b * 9216;
    for (int j = tid; j < 9216; j += 256) {
        const int oc = j / 144;
        const int p  = j % 144;
        const int ph = p / 12, pw = p % 12;
        const float* e = s_epi + oc * 576 + (2 * ph) * 24 + 2 * pw;
        const float v = fmaxf(fmaxf(e[0], e[1]), fmaxf(e[24], e[25]));
        outp[j] = to_tf32(fmaxf(v, 0.0f));
    }
}

// ============================================================================
// K2: fc1 split-K via tf32 mma.sync.  C[512,128] = A[512,9216] * W^T.
// A NCHW-flat (coalesced); B n-major pad 36 (coalesced, conflict-free).
// ============================================================================
__global__ void __launch_bounds__(256) fc1_tc(const float* __restrict__ wfc1)
{
    __shared__ float sA[64 * 32];     // swizzled [m][k]
    __shared__ float sB[128 * 36];    // n-major, pad 36

    const int mt   = blockIdx.x;    // 0..7
    const int ks   = blockIdx.y;    // 0..31
    const int tid  = threadIdx.x;
    const int wid  = tid >> 5;
    const int lane = tid & 31;
    const int g    = lane >> 2;
    const int tig  = lane & 3;
    const int m0   = mt * 64;
    const int k0   = ks * 288;
    const int mi   = wid & 3;       // m16-tile within the 64-row block
    const int nh   = wid >> 2;      // n-half (0 or 1)

    float acc[8][4];
#pragma unroll
    for (int n = 0; n < 8; n++)
#pragma unroll
        for (int q = 0; q < 4; q++) acc[n][q] = 0.0f;

#pragma unroll 1
    for (int kk = 0; kk < 288; kk += 32) {
        __syncthreads();
        for (int i = tid; i < 64 * 32; i += 256) {
            const int m = i >> 5, k = i & 31;
            sA[(m << 5) + (k ^ ((m & 7) << 2))] =
                g_pool2[(m0 + m) * 9216 + k0 + kk + k];         // coalesced
        }
        for (int i = tid; i < 128 * 32; i += 256) {
            const int n = i >> 5, k = i & 31;
            sB[n * 36 + k] = to_tf32(wfc1[n * 9216 + k0 + kk + k]);  // coalesced
        }
        __syncthreads();

#pragma unroll
        for (int kstep = 0; kstep < 4; kstep++) {
            const int kb = kstep * 8;
            const int r0 = mi * 16 + g, r1 = r0 + 8;
            const int c0 = kb + tig,   c1 = c0 + 4;
            const uint32_t a0 = f2u(sA[(r0 << 5) + ((c0 & 31) ^ ((r0 & 7) << 2))]);
            const uint32_t a1 = f2u(sA[(r1 << 5) + ((c0 & 31) ^ ((r1 & 7) << 2))]);
            const uint32_t a2 = f2u(sA[(r0 << 5) + ((c1 & 31) ^ ((r0 & 7) << 2))]);
            const uint32_t a3 = f2u(sA[(r1 << 5) + ((c1 & 31) ^ ((r1 & 7) << 2))]);
#pragma unroll
            for (int n = 0; n < 8; n++) {
                const int nn = nh * 64 + n * 8 + g;
                const uint32_t bb0 = f2u(sB[nn * 36 + c0]);
                const uint32_t bb1 = f2u(sB[nn * 36 + c1]);
                mma_tf32(acc[n], a0, a1, a2, a3, bb0, bb1);
            }
        }
    }

    float* P = g_fc1part + (ks * 512 + m0) * 128;
    const int r0 = mi * 16 + g;
#pragma unroll
    for (int n = 0; n < 8; n++) {
        const int c0 = nh * 64 + n * 8 + tig * 2;
        P[r0 * 128 + c0]           = acc[n][0];
        P[r0 * 128 + c0 + 1]       = acc[n][1];
        P[(r0 + 8) * 128 + c0]     = acc[n][2];
        P[(r0 + 8) * 128 + c0 + 1] = acc[n][3];
    }
}

// ============================================================================
// K3: reduce split-K partials + bias + relu + fc2 (128->10).
// ============================================================================
__global__ void __launch_bounds__(128) fc_tail(
    const float* __restrict__ b1,
    const float* __restrict__ w2,
    const float* __restrict__ b2,
    float* __restrict__ out)
{
    __shared__ float s_h[128];
    const int b   = blockIdx.x;
    const int tid = threadIdx.x;

    float s = 0.f;
#pragma unroll
    for (int ks = 0; ks < 32; ks++)
        s += g_fc1part[(ks * 512 + b) * 128 + tid];
    s_h[tid] = fmaxf(s + b1[tid], 0.0f);
    __syncthreads();

    if (tid < 10) {
        float acc = b2[tid];
        const float* w = w2 + tid * 128;
#pragma unroll 8
        for (int k = 0; k < 128; k++)
            acc = fmaf(s_h[k], w[k], acc);
        out[b * 10 + tid] = acc;
    }
}

// ============================================================================
extern "C" void kernel_launch(void* const* d_in, const int* in_sizes, int n_in,
                              void* d_out, int out_size)
{
    const float* x   = (const float*)d_in[0];
    const float* c1w = (const float*)d_in[1];
    const float* c1b = (const float*)d_in[2];
    const float* c2w = (const float*)d_in[3];
    const float* c2b = (const float*)d_in[4];
    const float* f1w = (const float*)d_in[5];
    const float* f1b = (const float*)d_in[6];
    const float* f2w = (const float*)d_in[7];
    const float* f2b = (const float*)d_in[8];
    float* out       = (float*)d_out;

    // 704*32 A + 9*2048 B + 54*54 img = 43876 floats = 175504 B dynamic smem
    const int smem = (704 * 32 + 9 * 2048 + 54 * 54) * (int)sizeof(float);
    cudaFuncSetAttribute(convs_fused,
                         cudaFuncAttributeMaxDynamicSharedMemorySize, smem);

    convs_fused<<<512, 256, smem>>>(x, c1w, c1b, c2w, c2b);

    dim3 g2(8, 32);
    fc1_tc<<<g2, 256>>>(f1w);

    fc_tail<<<512, 128>>>(f1b, f2w, f2b, out);
}

// round 6
// speedup vs baseline: 2.2396x; 1.0441x over previous
#include <cuda_runtime.h>
#include <cstdint>

// ---------------- scratch (device globals: allocation-free) ----------------
__device__ float g_pool2[512 * 64 * 144];       // conv2 out, NCHW flat [b][9216]
__device__ float g_fc1part[32 * 512 * 128];     // fc1 split-K partials

__device__ __forceinline__ float to_tf32(float x) {
    float r;
    asm("cvt.rna.tf32.f32 %0, %1;" : "=f"(r) : "f"(x));
    return r;
}
__device__ __forceinline__ uint32_t f2u(float x) { return __float_as_uint(x); }
__device__ __forceinline__ uint32_t smem_u32(const void* p) {
    return (uint32_t)__cvta_generic_to_shared(p);
}

// Legacy tensor-core MMA: m16n8k8 tf32, fp32 accum (baseline PTX, sm_80+).
__device__ __forceinline__ void mma_tf32(float c[4],
                                         uint32_t a0, uint32_t a1,
                                         uint32_t a2, uint32_t a3,
                                         uint32_t b0, uint32_t b1) {
    asm volatile(
        "mma.sync.aligned.m16n8k8.row.col.f32.tf32.tf32.f32 "
        "{%0,%1,%2,%3}, {%4,%5,%6,%7}, {%8,%9}, {%0,%1,%2,%3};"
        : "+f"(c[0]), "+f"(c[1]), "+f"(c[2]), "+f"(c[3])
        : "r"(a0), "r"(a1), "r"(a2), "r"(a3), "r"(b0), "r"(b1));
}

// ldmatrix x4 (baseline PTX, sm_75+): 4 m8n8 b16 tiles.
__device__ __forceinline__ void ldmx4(uint32_t r[4], uint32_t addr) {
    asm volatile(
        "ldmatrix.sync.aligned.m8n8.x4.shared.b16 {%0,%1,%2,%3}, [%4];"
        : "=r"(r[0]), "=r"(r[1]), "=r"(r[2]), "=r"(r[3]) : "r"(addr));
}

// ============================================================================
// K1 (fused): conv1+relu+pool (fp32, in-smem) -> conv2 via tf32 mma.sync
//             -> bias+relu+pool -> NCHW gmem.
// One CTA = one image, now 16 warps (512 threads) for 4 warps/SMSP latency
// hiding.  Warp (mg = wid&7, ng = wid>>3): 5 m16-tiles x 4 n8-tiles.
// conv2 GEMM: M = 640 pixel rows over the 26-grid (cols 24,25 garbage,
// dropped), N = 64 oc, K = 9 shifts x 32 ic; shift (di,dj) = A-row offset
// di*26+dj into the SAME staged conv1 output.
// ============================================================================
__global__ void __launch_bounds__(512, 1) convs_fused(
    const float* __restrict__ x,
    const float* __restrict__ w1,
    const float* __restrict__ b1,
    const float* __restrict__ w2,
    const float* __restrict__ b2)
{
    extern __shared__ float sm[];
    float* s_a   = sm;              // 704 rows x 32 floats (90112 B), swizzled
    float* s_b   = sm + 704 * 32;   // 9*64 rows x 32 floats (73728 B), n-major swizzled
    float* s_img = sm + 704 * 32 + 9 * 2048;  // 54*54 (11664 B)
    float* s_epi = sm;              // 64 oc x 576 pix (147456 B), reused
    __shared__ float s_w1[32 * 9];
    __shared__ float s_b1[32];
    __shared__ float s_bias[64];

    const int b    = blockIdx.x;
    const int tid  = threadIdx.x;
    const int wid  = tid >> 5;
    const int lane = tid & 31;
    const int g    = lane >> 2;     // groupID
    const int tig  = lane & 3;      // threadID_in_group
    const int mg   = wid & 7;       // m-group: 5 m16-tiles
    const int ng   = wid >> 3;      // n-half: 4 n8-tiles (32 cols)

    // ---- stage raw image + all weights (coalesced gmem reads) ----
    const float* xb = x + b * 54 * 54;
    for (int i = tid; i < 54 * 54; i += 512) s_img[i] = xb[i];
    for (int i = tid; i < 32 * 9; i += 512) s_w1[i] = w1[i];
    if (tid < 32) s_b1[tid] = b1[tid];
    if (tid < 64) s_bias[tid] = b2[tid];
    // conv2 weights -> n-major rows: s_b[(s*64+n)][k], group-swizzled by n&7.
    for (int i = tid; i < 64 * 32 * 9; i += 512) {
        const int n = i / 288;
        const int r = i % 288;
        const int k = r / 9;
        const int s = r % 9;
        s_b[((s * 64 + n) << 5) + ((((k >> 2) ^ (n & 7)) << 2) | (k & 3))] =
            to_tf32(w2[i]);
    }
    // zero-pad A rows [676, 704)
    for (int i = 676 * 32 + tid; i < 704 * 32; i += 512) {
        const int m = i >> 5, ic = i & 31;
        s_a[(m << 5) + (ic ^ ((m & 7) << 2))] = 0.0f;
    }
    __syncthreads();

    // ---- conv1 + relu + 2x2 pool (fp32) -> swizzled s_a rows ----
    for (int m = tid; m < 676; m += 512) {
        const int ph = m / 26, pw = m % 26;
        float in[4][4];
#pragma unroll
        for (int r = 0; r < 4; r++)
#pragma unroll
            for (int c = 0; c < 4; c++)
                in[r][c] = s_img[(2 * ph + r) * 54 + 2 * pw + c];
        float* arow = s_a + (m << 5);
        const uint32_t sw = (m & 7) << 2;
#pragma unroll 4
        for (int oc = 0; oc < 32; oc++) {
            const float* wp = &s_w1[oc * 9];
            float v00 = 0.f, v01 = 0.f, v10 = 0.f, v11 = 0.f;
#pragma unroll
            for (int i = 0; i < 3; i++)
#pragma unroll
                for (int j = 0; j < 3; j++) {
                    const float wv = wp[i * 3 + j];
                    v00 = fmaf(in[i][j],         wv, v00);
                    v01 = fmaf(in[i][j + 1],     wv, v01);
                    v10 = fmaf(in[i + 1][j],     wv, v10);
                    v11 = fmaf(in[i + 1][j + 1], wv, v11);
                }
            const float mx = fmaxf(fmaxf(v00, v01), fmaxf(v10, v11)) + s_b1[oc];
            arow[oc ^ sw] = to_tf32(fmaxf(mx, 0.0f));
        }
    }
    __syncthreads();

    // ---- conv2 mainloop ----
    float acc[5][4][4];
#pragma unroll
    for (int i = 0; i < 5; i++)
#pragma unroll
        for (int n = 0; n < 4; n++)
#pragma unroll
            for (int q = 0; q < 4; q++) acc[i][n][q] = 0.0f;

    const int mbase = mg * 80;      // 5 m16-tiles per m-group

    const uint32_t a_base = smem_u32(s_a);
    const uint32_t b_base = smem_u32(s_b);
    const int lrow = lane & 15;            // A local row within m16
    const int lhi  = lane >> 4;            // A col-group select (0/1)
    const int bnl  = (lane & 7) | (((lane >> 4) & 1) << 3);  // B local n row
    const int bch  = (lane >> 3) & 1;      // B chunk select (0/1)

#pragma unroll 1
    for (int s = 0; s < 9; s++) {
        const int roff = (s / 3) * 26 + (s % 3);
        const int arow = mbase + roff + lrow;
        const uint32_t a_row_addr = a_base + arow * 128;
        const int asw  = arow & 7;
        // warp's 32 n-cols start at ng*32: rows s*64 + ng*32 + p*16 + bnl
        const uint32_t b_row_addr = b_base + (s * 64 + ng * 32 + bnl) * 128;
        const int bsw  = (ng * 32 + bnl) & 7;

#pragma unroll
        for (int ks = 0; ks < 4; ks++) {
            const uint32_t aaddr =
                a_row_addr + ((uint32_t)((((ks << 1) + lhi) ^ asw)) << 4);
            const uint32_t baddr =
                b_row_addr + ((uint32_t)((((ks << 1) + bch) ^ bsw)) << 4);

            uint32_t a[5][4];
#pragma unroll
            for (int i = 0; i < 5; i++) ldmx4(a[i], aaddr + i * 2048);
            uint32_t bf[2][4];
#pragma unroll
            for (int p = 0; p < 2; p++) ldmx4(bf[p], baddr + p * 2048);

#pragma unroll
            for (int n = 0; n < 4; n++) {
                const uint32_t b0 = bf[n >> 1][(n & 1) * 2];
                const uint32_t b1 = bf[n >> 1][(n & 1) * 2 + 1];
#pragma unroll
                for (int i = 0; i < 5; i++)
                    mma_tf32(acc[i][n], a[i][0], a[i][1], a[i][2], a[i][3], b0, b1);
            }
        }
    }
    __syncthreads();   // MMA results in regs; staging smem dead -> reuse

    // ---- epilogue: scatter bias-added outputs to [oc][pix] smem ----
#pragma unroll
    for (int i = 0; i < 5; i++) {
        const int r0 = mbase + i * 16 + g;
        const int r1 = r0 + 8;
        const int h0 = r0 / 26, w0 = r0 % 26;
        const int h1 = r1 / 26, w1 = r1 % 26;
#pragma unroll
        for (int n = 0; n < 4; n++) {
            const int col0 = ng * 32 + n * 8 + tig * 2;
            if (h0 < 24 && w0 < 24) {
                const int pix = h0 * 24 + w0;
                s_epi[col0 * 576 + pix]       = acc[i][n][0] + s_bias[col0];
                s_epi[(col0 + 1) * 576 + pix] = acc[i][n][1] + s_bias[col0 + 1];
            }
            if (h1 < 24 && w1 < 24) {
                const int pix = h1 * 24 + w1;
                s_epi[col0 * 576 + pix]       = acc[i][n][2] + s_bias[col0];
                s_epi[(col0 + 1) * 576 + pix] = acc[i][n][3] + s_bias[col0 + 1];
            }
        }
    }
    __syncthreads();

    // ---- 2x2 maxpool + relu -> gmem NCHW flat [b][oc*144+p] (coalesced) ----
    float* outp = g_pool2 + b * 9216;
    for (int j = tid; j < 9216; j += 512) {
        const int oc = j / 144;
        const int p  = j % 144;
        const int ph = p / 12, pw = p % 12;
        const float* e = s_epi + oc * 576 + (2 * ph) * 24 + 2 * pw;
        const float v = fmaxf(fmaxf(e[0], e[1]), fmaxf(e[24], e[25]));
        outp[j] = to_tf32(fmaxf(v, 0.0f));
    }
}

// ============================================================================
// K2: fc1 split-K via tf32 mma.sync.  C[512,128] = A[512,9216] * W^T.
// A NCHW-flat (coalesced); B n-major pad 36 (coalesced, conflict-free).
// ============================================================================
__global__ void __launch_bounds__(256) fc1_tc(const float* __restrict__ wfc1)
{
    __shared__ float sA[64 * 32];     // swizzled [m][k]
    __shared__ float sB[128 * 36];    // n-major, pad 36

    const int mt   = blockIdx.x;    // 0..7
    const int ks   = blockIdx.y;    // 0..31
    const int tid  = threadIdx.x;
    const int wid  = tid >> 5;
    const int lane = tid & 31;
    const int g    = lane >> 2;
    const int tig  = lane & 3;
    const int m0   = mt * 64;
    const int k0   = ks * 288;
    const int mi   = wid & 3;       // m16-tile within the 64-row block
    const int nh   = wid >> 2;      // n-half (0 or 1)

    float acc[8][4];
#pragma unroll
    for (int n = 0; n < 8; n++)
#pragma unroll
        for (int q = 0; q < 4; q++) acc[n][q] = 0.0f;

#pragma unroll 1
    for (int kk = 0; kk < 288; kk += 32) {
        __syncthreads();
        for (int i = tid; i < 64 * 32; i += 256) {
            const int m = i >> 5, k = i & 31;
            sA[(m << 5) + (k ^ ((m & 7) << 2))] =
                g_pool2[(m0 + m) * 9216 + k0 + kk + k];         // coalesced
        }
        for (int i = tid; i < 128 * 32; i += 256) {
            const int n = i >> 5, k = i & 31;
            sB[n * 36 + k] = to_tf32(wfc1[n * 9216 + k0 + kk + k]);  // coalesced
        }
        __syncthreads();

#pragma unroll
        for (int kstep = 0; kstep < 4; kstep++) {
            const int kb = kstep * 8;
            const int r0 = mi * 16 + g, r1 = r0 + 8;
            const int c0 = kb + tig,   c1 = c0 + 4;
            const uint32_t a0 = f2u(sA[(r0 << 5) + ((c0 & 31) ^ ((r0 & 7) << 2))]);
            const uint32_t a1 = f2u(sA[(r1 << 5) + ((c0 & 31) ^ ((r1 & 7) << 2))]);
            const uint32_t a2 = f2u(sA[(r0 << 5) + ((c1 & 31) ^ ((r0 & 7) << 2))]);
            const uint32_t a3 = f2u(sA[(r1 << 5) + ((c1 & 31) ^ ((r1 & 7) << 2))]);
#pragma unroll
            for (int n = 0; n < 8; n++) {
                const int nn = nh * 64 + n * 8 + g;
                const uint32_t bb0 = f2u(sB[nn * 36 + c0]);
                const uint32_t bb1 = f2u(sB[nn * 36 + c1]);
                mma_tf32(acc[n], a0, a1, a2, a3, bb0, bb1);
            }
        }
    }

    float* P = g_fc1part + (ks * 512 + m0) * 128;
    const int r0 = mi * 16 + g;
#pragma unroll
    for (int n = 0; n < 8; n++) {
        const int c0 = nh * 64 + n * 8 + tig * 2;
        P[r0 * 128 + c0]           = acc[n][0];
        P[r0 * 128 + c0 + 1]       = acc[n][1];
        P[(r0 + 8) * 128 + c0]     = acc[n][2];
        P[(r0 + 8) * 128 + c0 + 1] = acc[n][3];
    }
}

// ============================================================================
// K3: reduce split-K partials + bias + relu + fc2 (128->10).
// ============================================================================
__global__ void __launch_bounds__(128) fc_tail(
    const float* __restrict__ b1,
    const float* __restrict__ w2,
    const float* __restrict__ b2,
    float* __restrict__ out)
{
    __shared__ float s_h[128];
    const int b   = blockIdx.x;
    const int tid = threadIdx.x;

    float s = 0.f;
#pragma unroll
    for (int ks = 0; ks < 32; ks++)
        s += g_fc1part[(ks * 512 + b) * 128 + tid];
    s_h[tid] = fmaxf(s + b1[tid], 0.0f);
    __syncthreads();

    if (tid < 10) {
        float acc = b2[tid];
        const float* w = w2 + tid * 128;
#pragma unroll 8
        for (int k = 0; k < 128; k++)
            acc = fmaf(s_h[k], w[k], acc);
        out[b * 10 + tid] = acc;
    }
}

// ============================================================================
extern "C" void kernel_launch(void* const* d_in, const int* in_sizes, int n_in,
                              void* d_out, int out_size)
{
    const float* x   = (const float*)d_in[0];
    const float* c1w = (const float*)d_in[1];
    const float* c1b = (const float*)d_in[2];
    const float* c2w = (const float*)d_in[3];
    const float* c2b = (const float*)d_in[4];
    const float* f1w = (const float*)d_in[5];
    const float* f1b = (const float*)d_in[6];
    const float* f2w = (const float*)d_in[7];
    const float* f2b = (const float*)d_in[8];
    float* out       = (float*)d_out;

    // 704*32 A + 9*2048 B + 54*54 img = 43876 floats = 175504 B dynamic smem
    const int smem = (704 * 32 + 9 * 2048 + 54 * 54) * (int)sizeof(float);
    cudaFuncSetAttribute(convs_fused,
                         cudaFuncAttributeMaxDynamicSharedMemorySize, smem);

    convs_fused<<<512, 512, smem>>>(x, c1w, c1b, c2w, c2b);

    dim3 g2(8, 32);
    fc1_tc<<<g2, 256>>>(f1w);

    fc_tail<<<512, 128>>>(f1b, f2w, f2b, out);
}

// round 7
// speedup vs baseline: 2.2567x; 1.0076x over previous
#include <cuda_runtime.h>
#include <cstdint>

// ---------------- scratch (device globals: allocation-free) ----------------
__device__ float g_pool2[512 * 64 * 144];       // conv2 out, NCHW flat [b][9216]
__device__ float g_fc1part[32 * 512 * 128];     // fc1 split-K partials

__device__ __forceinline__ float to_tf32(float x) {
    float r;
    asm("cvt.rna.tf32.f32 %0, %1;" : "=f"(r) : "f"(x));
    return r;
}
__device__ __forceinline__ uint32_t f2u(float x) { return __float_as_uint(x); }
__device__ __forceinline__ uint32_t smem_u32(const void* p) {
    return (uint32_t)__cvta_generic_to_shared(p);
}
__device__ __forceinline__ uint64_t pack2(float lo, float hi) {
    uint64_t r;
    asm("mov.b64 %0, {%1, %2};" : "=l"(r) : "f"(lo), "f"(hi));
    return r;
}
// Packed dual-fp32 FMA (PTX ISA sm_100+ base feature; maps to B300 FFMA2).
__device__ __forceinline__ void fma2(uint64_t& d, uint64_t a, uint64_t b) {
    asm("fma.rn.f32x2 %0, %1, %2, %0;" : "+l"(d) : "l"(a), "l"(b));
}
__device__ __forceinline__ void unpack2(uint64_t v, float& lo, float& hi) {
    uint32_t l, h;
    asm("mov.b64 {%0, %1}, %2;" : "=r"(l), "=r"(h) : "l"(v));
    lo = __uint_as_float(l);
    hi = __uint_as_float(h);
}

// Legacy tensor-core MMA: m16n8k8 tf32, fp32 accum (baseline PTX, sm_80+).
__device__ __forceinline__ void mma_tf32(float c[4],
                                         uint32_t a0, uint32_t a1,
                                         uint32_t a2, uint32_t a3,
                                         uint32_t b0, uint32_t b1) {
    asm volatile(
        "mma.sync.aligned.m16n8k8.row.col.f32.tf32.tf32.f32 "
        "{%0,%1,%2,%3}, {%4,%5,%6,%7}, {%8,%9}, {%0,%1,%2,%3};"
        : "+f"(c[0]), "+f"(c[1]), "+f"(c[2]), "+f"(c[3])
        : "r"(a0), "r"(a1), "r"(a2), "r"(a3), "r"(b0), "r"(b1));
}

// ldmatrix x4 (baseline PTX, sm_75+): 4 m8n8 b16 tiles.
__device__ __forceinline__ void ldmx4(uint32_t r[4], uint32_t addr) {
    asm volatile(
        "ldmatrix.sync.aligned.m8n8.x4.shared.b16 {%0,%1,%2,%3}, [%4];"
        : "=r"(r[0]), "=r"(r[1]), "=r"(r[2]), "=r"(r[3]) : "r"(addr));
}

// ============================================================================
// K1 (fused): conv1+relu+pool (packed f32x2) -> conv2 via tf32 mma.sync
//             -> bias+relu+pool -> NCHW gmem.
// One CTA = one image, 16 warps. Phase overlap: warps 0-7 run conv1 while
// warps 8-15 stage conv2 weights (disjoint pipes: FMA vs LSU/ALU).
// conv2 GEMM: M = 640 pixel rows over the 26-grid (cols 24,25 garbage,
// dropped), N = 64 oc, K = 9 shifts x 32 ic; shift (di,dj) = A-row offset
// di*26+dj into the SAME staged conv1 output.
// ============================================================================
__global__ void __launch_bounds__(512, 1) convs_fused(
    const float* __restrict__ x,
    const float* __restrict__ w1,
    const float* __restrict__ b1,
    const float* __restrict__ w2,
    const float* __restrict__ b2)
{
    extern __shared__ float sm[];
    float* s_a   = sm;              // 704 rows x 32 floats (90112 B), swizzled
    float* s_b   = sm + 704 * 32;   // 9*64 rows x 32 floats (73728 B), n-major swizzled
    float* s_img = sm + 704 * 32 + 9 * 2048;  // 54*54 (11664 B)
    float* s_epi = sm;              // 64 oc x 576 pix (147456 B), reused
    __shared__ uint64_t s_w1d[32 * 9];   // conv1 weights duplicated (w,w)
    __shared__ float s_b1[32];
    __shared__ float s_bias[64];

    const int b    = blockIdx.x;
    const int tid  = threadIdx.x;
    const int wid  = tid >> 5;
    const int lane = tid & 31;
    const int g    = lane >> 2;     // groupID
    const int tig  = lane & 3;      // threadID_in_group
    const int mg   = wid & 7;       // m-group: 5 m16-tiles
    const int ng   = wid >> 3;      // n-half: 4 n8-tiles (32 cols)

    // ---- phase 0 (all warps): image (float4) + conv1 weights + biases ----
    {
        const float4* xb4 = (const float4*)(x + b * 54 * 54);
        float4* si4 = (float4*)s_img;
        for (int i = tid; i < 729; i += 512) si4[i] = xb4[i];
    }
    for (int i = tid; i < 32 * 9; i += 512) {
        const float wv = w1[i];
        s_w1d[i] = pack2(wv, wv);
    }
    if (tid < 32) s_b1[tid] = b1[tid];
    if (tid < 64) s_bias[tid] = b2[tid];
    __syncthreads();

    if (tid < 256) {
        // ---- phase 1a (warps 0-7): conv1 + relu + pool -> swizzled s_a ----
        for (int m = tid; m < 676; m += 256) {
            const int ph = m / 26, pw = m % 26;
            float in[4][4];
#pragma unroll
            for (int r = 0; r < 4; r++)
#pragma unroll
                for (int c = 0; c < 4; c++)
                    in[r][c] = s_img[(2 * ph + r) * 54 + 2 * pw + c];
            // packed horizontal pairs (in[r][j], in[r][j+1])
            uint64_t ap[4][3];
#pragma unroll
            for (int r = 0; r < 4; r++)
#pragma unroll
                for (int j = 0; j < 3; j++)
                    ap[r][j] = pack2(in[r][j], in[r][j + 1]);

            float* arow = s_a + (m << 5);
            const uint32_t sw = (m & 7) << 2;
#pragma unroll 4
            for (int oc = 0; oc < 32; oc++) {
                uint64_t v0 = 0ull, v1 = 0ull;   // (v00,v01), (v10,v11)
#pragma unroll
                for (int t = 0; t < 9; t++) {
                    const uint64_t wv2 = s_w1d[oc * 9 + t];
                    fma2(v0, ap[t / 3][t % 3], wv2);
                    fma2(v1, ap[t / 3 + 1][t % 3], wv2);
                }
                float v00, v01, v10, v11;
                unpack2(v0, v00, v01);
                unpack2(v1, v10, v11);
                const float mx =
                    fmaxf(fmaxf(v00, v01), fmaxf(v10, v11)) + s_b1[oc];
                arow[oc ^ sw] = to_tf32(fmaxf(mx, 0.0f));
            }
        }
    } else {
        // ---- phase 1b (warps 8-15): conv2 weights + A zero-pad ----
        const int t2 = tid - 256;
        // n-major rows: s_b[(s*64+n)][k], 16B-group swizzled by n&7.
        for (int i = t2; i < 64 * 32 * 9; i += 256) {
            const int n = i / 288;
            const int r = i % 288;
            const int k = r / 9;
            const int s = r % 9;
            s_b[((s * 64 + n) << 5) + ((((k >> 2) ^ (n & 7)) << 2) | (k & 3))] =
                to_tf32(w2[i]);
        }
        for (int i = 676 * 32 + t2; i < 704 * 32; i += 256) {
            const int m = i >> 5, ic = i & 31;
            s_a[(m << 5) + (ic ^ ((m & 7) << 2))] = 0.0f;
        }
    }
    __syncthreads();

    // ---- conv2 mainloop ----
    float acc[5][4][4];
#pragma unroll
    for (int i = 0; i < 5; i++)
#pragma unroll
        for (int n = 0; n < 4; n++)
#pragma unroll
            for (int q = 0; q < 4; q++) acc[i][n][q] = 0.0f;

    const int mbase = mg * 80;      // 5 m16-tiles per m-group

    const uint32_t a_base = smem_u32(s_a);
    const uint32_t b_base = smem_u32(s_b);
    const int lrow = lane & 15;            // A local row within m16
    const int lhi  = lane >> 4;            // A col-group select (0/1)
    const int bnl  = (lane & 7) | (((lane >> 4) & 1) << 3);  // B local n row
    const int bch  = (lane >> 3) & 1;      // B chunk select (0/1)

#pragma unroll 1
    for (int s = 0; s < 9; s++) {
        const int roff = (s / 3) * 26 + (s % 3);
        const int arow = mbase + roff + lrow;
        const uint32_t a_row_addr = a_base + arow * 128;
        const int asw  = arow & 7;
        const uint32_t b_row_addr = b_base + (s * 64 + ng * 32 + bnl) * 128;
        const int bsw  = (ng * 32 + bnl) & 7;

#pragma unroll
        for (int ks = 0; ks < 4; ks++) {
            const uint32_t aaddr =
                a_row_addr + ((uint32_t)((((ks << 1) + lhi) ^ asw)) << 4);
            const uint32_t baddr =
                b_row_addr + ((uint32_t)((((ks << 1) + bch) ^ bsw)) << 4);

            uint32_t a[5][4];
#pragma unroll
            for (int i = 0; i < 5; i++) ldmx4(a[i], aaddr + i * 2048);
            uint32_t bf[2][4];
#pragma unroll
            for (int p = 0; p < 2; p++) ldmx4(bf[p], baddr + p * 2048);

#pragma unroll
            for (int n = 0; n < 4; n++) {
                const uint32_t b0 = bf[n >> 1][(n & 1) * 2];
                const uint32_t b1 = bf[n >> 1][(n & 1) * 2 + 1];
#pragma unroll
                for (int i = 0; i < 5; i++)
                    mma_tf32(acc[i][n], a[i][0], a[i][1], a[i][2], a[i][3], b0, b1);
            }
        }
    }
    __syncthreads();   // MMA results in regs; staging smem dead -> reuse

    // ---- epilogue: scatter bias-added outputs to [oc][pix] smem ----
#pragma unroll
    for (int i = 0; i < 5; i++) {
        const int r0 = mbase + i * 16 + g;
        const int r1 = r0 + 8;
        const int h0 = r0 / 26, w0 = r0 % 26;
        const int h1 = r1 / 26, w1 = r1 % 26;
#pragma unroll
        for (int n = 0; n < 4; n++) {
            const int col0 = ng * 32 + n * 8 + tig * 2;
            if (h0 < 24 && w0 < 24) {
                const int pix = h0 * 24 + w0;
                s_epi[col0 * 576 + pix]       = acc[i][n][0] + s_bias[col0];
                s_epi[(col0 + 1) * 576 + pix] = acc[i][n][1] + s_bias[col0 + 1];
            }
            if (h1 < 24 && w1 < 24) {
                const int pix = h1 * 24 + w1;
                s_epi[col0 * 576 + pix]       = acc[i][n][2] + s_bias[col0];
                s_epi[(col0 + 1) * 576 + pix] = acc[i][n][3] + s_bias[col0 + 1];
            }
        }
    }
    __syncthreads();

    // ---- 2x2 maxpool + relu -> gmem NCHW flat [b][oc*144+p] (coalesced) ----
    float* outp = g_pool2 + b * 9216;
    for (int j = tid; j < 9216; j += 512) {
        const int oc = j / 144;
        const int p  = j % 144;
        const int ph = p / 12, pw = p % 12;
        const float* e = s_epi + oc * 576 + (2 * ph) * 24 + 2 * pw;
        const float v = fmaxf(fmaxf(e[0], e[1]), fmaxf(e[24], e[25]));
        outp[j] = to_tf32(fmaxf(v, 0.0f));
    }
}

// ============================================================================
// K2: fc1 split-K via tf32 mma.sync.  C[512,128] = A[512,9216] * W^T.
// A NCHW-flat (coalesced); B n-major pad 36 (coalesced, conflict-free).
// ============================================================================
__global__ void __launch_bounds__(256) fc1_tc(const float* __restrict__ wfc1)
{
    __shared__ float sA[64 * 32];     // swizzled [m][k]
    __shared__ float sB[128 * 36];    // n-major, pad 36

    const int mt   = blockIdx.x;    // 0..7
    const int ks   = blockIdx.y;    // 0..31
    const int tid  = threadIdx.x;
    const int wid  = tid >> 5;
    const int lane = tid & 31;
    const int g    = lane >> 2;
    const int tig  = lane & 3;
    const int m0   = mt * 64;
    const int k0   = ks * 288;
    const int mi   = wid & 3;       // m16-tile within the 64-row block
    const int nh   = wid >> 2;      // n-half (0 or 1)

    float acc[8][4];
#pragma unroll
    for (int n = 0; n < 8; n++)
#pragma unroll
        for (int q = 0; q < 4; q++) acc[n][q] = 0.0f;

#pragma unroll 1
    for (int kk = 0; kk < 288; kk += 32) {
        __syncthreads();
        for (int i = tid; i < 64 * 32; i += 256) {
            const int m = i >> 5, k = i & 31;
            sA[(m << 5) + (k ^ ((m & 7) << 2))] =
                g_pool2[(m0 + m) * 9216 + k0 + kk + k];         // coalesced
        }
        for (int i = tid; i < 128 * 32; i += 256) {
            const int n = i >> 5, k = i & 31;
            sB[n * 36 + k] = to_tf32(wfc1[n * 9216 + k0 + kk + k]);  // coalesced
        }
        __syncthreads();

#pragma unroll
        for (int kstep = 0; kstep < 4; kstep++) {
            const int kb = kstep * 8;
            const int r0 = mi * 16 + g, r1 = r0 + 8;
            const int c0 = kb + tig,   c1 = c0 + 4;
            const uint32_t a0 = f2u(sA[(r0 << 5) + ((c0 & 31) ^ ((r0 & 7) << 2))]);
            const uint32_t a1 = f2u(sA[(r1 << 5) + ((c0 & 31) ^ ((r1 & 7) << 2))]);
            const uint32_t a2 = f2u(sA[(r0 << 5) + ((c1 & 31) ^ ((r0 & 7) << 2))]);
            const uint32_t a3 = f2u(sA[(r1 << 5) + ((c1 & 31) ^ ((r1 & 7) << 2))]);
#pragma unroll
            for (int n = 0; n < 8; n++) {
                const int nn = nh * 64 + n * 8 + g;
                const uint32_t bb0 = f2u(sB[nn * 36 + c0]);
                const uint32_t bb1 = f2u(sB[nn * 36 + c1]);
                mma_tf32(acc[n], a0, a1, a2, a3, bb0, bb1);
            }
        }
    }

    float* P = g_fc1part + (ks * 512 + m0) * 128;
    const int r0 = mi * 16 + g;
#pragma unroll
    for (int n = 0; n < 8; n++) {
        const int c0 = nh * 64 + n * 8 + tig * 2;
        P[r0 * 128 + c0]           = acc[n][0];
        P[r0 * 128 + c0 + 1]       = acc[n][1];
        P[(r0 + 8) * 128 + c0]     = acc[n][2];
        P[(r0 + 8) * 128 + c0 + 1] = acc[n][3];
    }
}

// ============================================================================
// K3: reduce split-K partials + bias + relu + fc2 (128->10).
// ============================================================================
__global__ void __launch_bounds__(128) fc_tail(
    const float* __restrict__ b1,
    const float* __restrict__ w2,
    const float* __restrict__ b2,
    float* __restrict__ out)
{
    __shared__ float s_h[128];
    const int b   = blockIdx.x;
    const int tid = threadIdx.x;

    float s = 0.f;
#pragma unroll
    for (int ks = 0; ks < 32; ks++)
        s += g_fc1part[(ks * 512 + b) * 128 + tid];
    s_h[tid] = fmaxf(s + b1[tid], 0.0f);
    __syncthreads();

    if (tid < 10) {
        float acc = b2[tid];
        const float* w = w2 + tid * 128;
#pragma unroll 8
        for (int k = 0; k < 128; k++)
            acc = fmaf(s_h[k], w[k], acc);
        out[b * 10 + tid] = acc;
    }
}

// ============================================================================
extern "C" void kernel_launch(void* const* d_in, const int* in_sizes, int n_in,
                              void* d_out, int out_size)
{
    const float* x   = (const float*)d_in[0];
    const float* c1w = (const float*)d_in[1];
    const float* c1b = (const float*)d_in[2];
    const float* c2w = (const float*)d_in[3];
    const float* c2b = (const float*)d_in[4];
    const float* f1w = (const float*)d_in[5];
    const float* f1b = (const float*)d_in[6];
    const float* f2w = (const float*)d_in[7];
    const float* f2b = (const float*)d_in[8];
    float* out       = (float*)d_out;

    // 704*32 A + 9*2048 B + 54*54 img = 43876 floats = 175504 B dynamic smem
    const int smem = (704 * 32 + 9 * 2048 + 54 * 54) * (int)sizeof(float);
    cudaFuncSetAttribute(convs_fused,
                         cudaFuncAttributeMaxDynamicSharedMemorySize, smem);

    convs_fused<<<512, 512, smem>>>(x, c1w, c1b, c2w, c2b);

    dim3 g2(8, 32);
    fc1_tc<<<g2, 256>>>(f1w);

    fc_tail<<<512, 128>>>(f1b, f2w, f2b, out);
}

// round 8
// speedup vs baseline: 2.5973x; 1.1509x over previous
#include <cuda_runtime.h>
#include <cuda_fp16.h>
#include <cstdint>

// ---------------- scratch (device globals: allocation-free) ----------------
__device__ __half g_pool2h[512 * 9216];         // conv2 out, NCHW flat, fp16
__device__ float  g_fc1part[16 * 512 * 128];    // fc1 split-K partials

__device__ __forceinline__ uint32_t smem_u32(const void* p) {
    return (uint32_t)__cvta_generic_to_shared(p);
}
__device__ __forceinline__ uint64_t pack2(float lo, float hi) {
    uint64_t r;
    asm("mov.b64 %0, {%1, %2};" : "=l"(r) : "f"(lo), "f"(hi));
    return r;
}
__device__ __forceinline__ void fma2(uint64_t& d, uint64_t a, uint64_t b) {
    asm("fma.rn.f32x2 %0, %1, %2, %0;" : "+l"(d) : "l"(a), "l"(b));
}
__device__ __forceinline__ void unpack2(uint64_t v, float& lo, float& hi) {
    uint32_t l, h;
    asm("mov.b64 {%0, %1}, %2;" : "=r"(l), "=r"(h) : "l"(v));
    lo = __uint_as_float(l);
    hi = __uint_as_float(h);
}
// packed f32 pair -> f16x2 (hi -> bits[31:16], lo -> bits[15:0])
__device__ __forceinline__ uint32_t cvt_f16x2(float hi, float lo) {
    uint32_t r;
    asm("cvt.rn.f16x2.f32 %0, %1, %2;" : "=r"(r) : "f"(hi), "f"(lo));
    return r;
}

// fp16 tensor-core MMA, fp32 accum (baseline PTX, sm_80+). Same 11-bit
// significand as tf32 -> same numerics, 2x MAC per instruction.
__device__ __forceinline__ void mma_f16(float c[4],
                                        uint32_t a0, uint32_t a1,
                                        uint32_t a2, uint32_t a3,
                                        uint32_t b0, uint32_t b1) {
    asm volatile(
        "mma.sync.aligned.m16n8k16.row.col.f32.f16.f16.f32 "
        "{%0,%1,%2,%3}, {%4,%5,%6,%7}, {%8,%9}, {%0,%1,%2,%3};"
        : "+f"(c[0]), "+f"(c[1]), "+f"(c[2]), "+f"(c[3])
        : "r"(a0), "r"(a1), "r"(a2), "r"(a3), "r"(b0), "r"(b1));
}
__device__ __forceinline__ void ldmx4(uint32_t r[4], uint32_t addr) {
    asm volatile(
        "ldmatrix.sync.aligned.m8n8.x4.shared.b16 {%0,%1,%2,%3}, [%4];"
        : "=r"(r[0]), "=r"(r[1]), "=r"(r[2]), "=r"(r[3]) : "r"(addr));
}
__device__ __forceinline__ void ldmx2(uint32_t& r0, uint32_t& r1, uint32_t addr) {
    asm volatile(
        "ldmatrix.sync.aligned.m8n8.x2.shared.b16 {%0,%1}, [%2];"
        : "=r"(r0), "=r"(r1) : "r"(addr));
}

// ============================================================================
// K1 (fused): conv1+relu+pool (f32x2 FMA) -> conv2 via fp16 m16n8k16 mma
//             -> bias+relu+pool -> NCHW fp16 gmem.
// One CTA = one image, 16 warps. Warps 0-7: conv1; warps 8-15: stage conv2 W.
// conv2 GEMM: M = 640 pixel rows over the 26-grid, N = 64 oc,
// K = 9 shifts x 32 ic (2 k16-steps per shift).
// A/B smem: 64B rows; swizzle chunk c ^= (row>>1)&3 -> conflict-free LDSM.
// ============================================================================
__global__ void __launch_bounds__(512, 1) convs_fused(
    const float* __restrict__ x,
    const float* __restrict__ w1,
    const float* __restrict__ b1,
    const float* __restrict__ w2,
    const float* __restrict__ b2)
{
    extern __shared__ char smc[];
    __half* s_a   = (__half*)smc;                 // 704 rows x 64B = 45056 B
    __half* s_b   = (__half*)(smc + 45056);       // 9*64 rows x 64B = 36864 B
    float*  s_img = (float*)(smc + 81920);        // 54*54 f32 = 11664 B
    float*  s_epi = (float*)smc;                  // 64 x 576 f32 (reuse)
    __shared__ uint64_t s_w1d[32 * 9];            // conv1 weights (w,w)
    __shared__ float s_b1[32];
    __shared__ float s_bias[64];

    const int b    = blockIdx.x;
    const int tid  = threadIdx.x;
    const int wid  = tid >> 5;
    const int lane = tid & 31;
    const int g    = lane >> 2;
    const int tig  = lane & 3;
    const int mg   = wid & 7;       // m-group: 5 m16-tiles
    const int ng   = wid >> 3;      // n-half: 4 n8-tiles

    // ---- phase 0: image (float4) + conv1 weights + biases ----
    {
        const float4* xb4 = (const float4*)(x + b * 54 * 54);
        float4* si4 = (float4*)s_img;
        for (int i = tid; i < 729; i += 512) si4[i] = xb4[i];
    }
    for (int i = tid; i < 32 * 9; i += 512) {
        const float wv = w1[i];
        s_w1d[i] = pack2(wv, wv);
    }
    if (tid < 32) s_b1[tid] = b1[tid];
    if (tid < 64) s_bias[tid] = b2[tid];
    __syncthreads();

    if (tid < 256) {
        // ---- warps 0-7: conv1 + relu + pool -> fp16 swizzled s_a ----
        for (int m = tid; m < 676; m += 256) {
            const int ph = m / 26, pw = m % 26;
            float in[4][4];
#pragma unroll
            for (int r = 0; r < 4; r++)
#pragma unroll
                for (int c = 0; c < 4; c++)
                    in[r][c] = s_img[(2 * ph + r) * 54 + 2 * pw + c];
            uint64_t ap[4][3];
#pragma unroll
            for (int r = 0; r < 4; r++)
#pragma unroll
                for (int j = 0; j < 3; j++)
                    ap[r][j] = pack2(in[r][j], in[r][j + 1]);

            char* arow = (char*)s_a + m * 64;
            const int sw2 = (m >> 1) & 3;
#pragma unroll 2
            for (int oc2 = 0; oc2 < 16; oc2++) {
                const int oca = oc2 * 2, ocb = oca + 1;
                uint64_t va0 = 0ull, va1 = 0ull, vb0 = 0ull, vb1 = 0ull;
#pragma unroll
                for (int t = 0; t < 9; t++) {
                    const uint64_t wa = s_w1d[oca * 9 + t];
                    const uint64_t wb = s_w1d[ocb * 9 + t];
                    fma2(va0, ap[t / 3][t % 3], wa);
                    fma2(va1, ap[t / 3 + 1][t % 3], wa);
                    fma2(vb0, ap[t / 3][t % 3], wb);
                    fma2(vb1, ap[t / 3 + 1][t % 3], wb);
                }
                float a00, a01, a10, a11, b00, b01, b10, b11;
                unpack2(va0, a00, a01); unpack2(va1, a10, a11);
                unpack2(vb0, b00, b01); unpack2(vb1, b10, b11);
                float ma = fmaxf(fmaxf(a00, a01), fmaxf(a10, a11)) + s_b1[oca];
                float mb = fmaxf(fmaxf(b00, b01), fmaxf(b10, b11)) + s_b1[ocb];
                ma = fmaxf(ma, 0.0f);
                mb = fmaxf(mb, 0.0f);
                const uint32_t h2 = cvt_f16x2(mb, ma);   // hi=odd oc, lo=even oc
                *(uint32_t*)(arow +
                    ((((oca >> 3) ^ sw2) << 4) | ((oca & 7) << 1))) = h2;
            }
        }
    } else {
        // ---- warps 8-15: conv2 weights (fp16, swizzled) + A zero-pad ----
        const int t2 = tid - 256;
        for (int i = t2; i < 64 * 32 * 9; i += 256) {
            const int n = i / 288;
            const int r = i % 288;
            const int k = r / 9;
            const int s = r % 9;
            const int row = s * 64 + n;
            *(__half*)((char*)s_b + row * 64 +
                ((((k >> 3) ^ ((n >> 1) & 3)) << 4) | ((k & 7) << 1))) =
                __float2half_rn(w2[i]);
        }
        for (int i = 676 * 16 + t2; i < 704 * 16; i += 256)
            ((uint32_t*)s_a)[i] = 0u;     // zero rows 676..703 (any swizzle)
    }
    __syncthreads();

    // ---- conv2 mainloop: 9 shifts x 2 k16-steps, fp16 MMA ----
    float acc[5][4][4];
#pragma unroll
    for (int i = 0; i < 5; i++)
#pragma unroll
        for (int n = 0; n < 4; n++)
#pragma unroll
            for (int q = 0; q < 4; q++) acc[i][n][q] = 0.0f;

    const int mbase = mg * 80;

    const uint32_t a_base = smem_u32(s_a);
    const uint32_t b_base = smem_u32(s_b);
    const int lrow15 = lane & 15;
    const int lhi    = lane >> 4;                  // A chunk select
    const int bch    = (lane >> 3) & 1;            // B chunk select
    const int bsw    = ((lane & 7) >> 1) & 3;      // B swizzle (lane-const)
    const uint32_t b_lane_base = b_base + (ng * 32 + (lane & 7)) * 64;

#pragma unroll 1
    for (int s = 0; s < 9; s++) {
        const int roff = (s / 3) * 26 + (s % 3);
        const int arow = mbase + roff + lrow15;
        const int asw  = (arow >> 1) & 3;
        const uint32_t a_row_addr = a_base + arow * 64;
        const uint32_t b_row_addr = b_lane_base + s * 4096;

#pragma unroll
        for (int ks = 0; ks < 2; ks++) {
            const uint32_t aaddr =
                a_row_addr + ((uint32_t)((((ks << 1) + lhi) ^ asw)) << 4);
            const uint32_t bk =
                b_row_addr + ((uint32_t)((((ks << 1) + bch) ^ bsw)) << 4);

            uint32_t a[5][4];
#pragma unroll
            for (int i = 0; i < 5; i++) ldmx4(a[i], aaddr + i * 1024);

#pragma unroll
            for (int nt = 0; nt < 4; nt++) {
                uint32_t b0, b1;
                ldmx2(b0, b1, bk + nt * 512);
#pragma unroll
                for (int i = 0; i < 5; i++)
                    mma_f16(acc[i][nt], a[i][0], a[i][1], a[i][2], a[i][3], b0, b1);
            }
        }
    }
    __syncthreads();   // results in regs; staging smem dead -> reuse as s_epi

    // ---- epilogue: scatter bias-added outputs to [oc][pix] smem ----
#pragma unroll
    for (int i = 0; i < 5; i++) {
        const int r0 = mbase + i * 16 + g;
        const int r1 = r0 + 8;
        const int h0 = r0 / 26, w0 = r0 % 26;
        const int h1 = r1 / 26, w1 = r1 % 26;
#pragma unroll
        for (int n = 0; n < 4; n++) {
            const int col0 = ng * 32 + n * 8 + tig * 2;
            if (h0 < 24 && w0 < 24) {
                const int pix = h0 * 24 + w0;
                s_epi[col0 * 576 + pix]       = acc[i][n][0] + s_bias[col0];
                s_epi[(col0 + 1) * 576 + pix] = acc[i][n][1] + s_bias[col0 + 1];
            }
            if (h1 < 24 && w1 < 24) {
                const int pix = h1 * 24 + w1;
                s_epi[col0 * 576 + pix]       = acc[i][n][2] + s_bias[col0];
                s_epi[(col0 + 1) * 576 + pix] = acc[i][n][3] + s_bias[col0 + 1];
            }
        }
    }
    __syncthreads();

    // ---- 2x2 maxpool + relu -> fp16 NCHW flat [b][oc*144+p] (coalesced) ----
    __half* outp = g_pool2h + b * 9216;
    for (int j = tid; j < 9216; j += 512) {
        const int oc = j / 144;
        const int p  = j % 144;
        const int ph = p / 12, pw = p % 12;
        const float* e = s_epi + oc * 576 + (2 * ph) * 24 + 2 * pw;
        const float v = fmaxf(fmaxf(e[0], e[1]), fmaxf(e[24], e[25]));
        outp[j] = __float2half_rn(fmaxf(v, 0.0f));
    }
}

// ============================================================================
// K2: fc1 split-K (16 ways) via fp16 m16n8k16.  C[512,128] = A[512,9216]*W^T.
// A = g_pool2h fp16 (coalesced half2 loads); B cvt'd to fp16 in staging.
// grid = (8 m-tiles of 64, 16 k-chunks of 576), 256 thr = 8 warps.
// ============================================================================
__global__ void __launch_bounds__(256) fc1_tc(const float* __restrict__ wfc1)
{
    __shared__ __half sA[64 * 32];     // 64B rows, swizzled
    __shared__ __half sB[128 * 32];    // 64B rows, swizzled

    const int mt   = blockIdx.x;    // 0..7
    const int ks   = blockIdx.y;    // 0..15
    const int tid  = threadIdx.x;
    const int wid  = tid >> 5;
    const int lane = tid & 31;
    const int m0   = mt * 64;
    const int k0   = ks * 576;
    const int mi   = wid & 3;       // m16-tile
    const int nh   = wid >> 2;      // n-half (64 cols)

    const int lrow15 = lane & 15;
    const int lhi    = lane >> 4;
    const int bch    = (lane >> 3) & 1;
    const int bsw    = ((lane & 7) >> 1) & 3;

    const uint32_t sA_base = smem_u32(sA);
    const uint32_t sB_base = smem_u32(sB);
    const int arow = mi * 16 + lrow15;
    const int asw  = (arow >> 1) & 3;
    const uint32_t a_row_addr = sA_base + arow * 64;
    const uint32_t b_row_addr = sB_base + (nh * 64 + (lane & 7)) * 64;

    float acc[8][4];
#pragma unroll
    for (int n = 0; n < 8; n++)
#pragma unroll
        for (int q = 0; q < 4; q++) acc[n][q] = 0.0f;

#pragma unroll 1
    for (int kk = 0; kk < 576; kk += 32) {
        __syncthreads();
        // A: 64 m x 16 half2 units, coalesced fp16 gmem reads
        for (int i = tid; i < 64 * 16; i += 256) {
            const int m = i >> 4, k = (i & 15) * 2;
            const uint32_t v =
                *(const uint32_t*)(g_pool2h + (m0 + m) * 9216 + k0 + kk + k);
            *(uint32_t*)((char*)sA + m * 64 +
                ((((k >> 3) ^ ((m >> 1) & 3)) << 4) | ((k & 7) << 1))) = v;
        }
        // B: 128 n x 16 half2 units, float2 gmem reads + cvt
        for (int i = tid; i < 128 * 16; i += 256) {
            const int n = i >> 4, k = (i & 15) * 2;
            const float2 wv = *(const float2*)(wfc1 + n * 9216 + k0 + kk + k);
            *(uint32_t*)((char*)sB + n * 64 +
                ((((k >> 3) ^ ((n >> 1) & 3)) << 4) | ((k & 7) << 1))) =
                cvt_f16x2(wv.y, wv.x);
        }
        __syncthreads();

#pragma unroll
        for (int kstep = 0; kstep < 2; kstep++) {
            uint32_t a[4];
            ldmx4(a, a_row_addr +
                     ((uint32_t)((((kstep << 1) + lhi) ^ asw)) << 4));
            const uint32_t bk =
                b_row_addr + ((uint32_t)((((kstep << 1) + bch) ^ bsw)) << 4);
#pragma unroll
            for (int nt = 0; nt < 8; nt++) {
                uint32_t b0, b1;
                ldmx2(b0, b1, bk + nt * 512);
                mma_f16(acc[nt], a[0], a[1], a[2], a[3], b0, b1);
            }
        }
    }

    float* P = g_fc1part + (ks * 512 + m0) * 128;
    const int g   = lane >> 2;
    const int tig = lane & 3;
    const int r0  = mi * 16 + g;
#pragma unroll
    for (int n = 0; n < 8; n++) {
        const int c0 = nh * 64 + n * 8 + tig * 2;
        P[r0 * 128 + c0]           = acc[n][0];
        P[r0 * 128 + c0 + 1]       = acc[n][1];
        P[(r0 + 8) * 128 + c0]     = acc[n][2];
        P[(r0 + 8) * 128 + c0 + 1] = acc[n][3];
    }
}

// ============================================================================
// K3: reduce split-K partials + bias + relu + fc2 (128->10).
// ============================================================================
__global__ void __launch_bounds__(128) fc_tail(
    const float* __restrict__ b1,
    const float* __restrict__ w2,
    const float* __restrict__ b2,
    float* __restrict__ out)
{
    __shared__ float s_h[128];
    const int b   = blockIdx.x;
    const int tid = threadIdx.x;

    float s = 0.f;
#pragma unroll
    for (int ks = 0; ks < 16; ks++)
        s += g_fc1part[(ks * 512 + b) * 128 + tid];
    s_h[tid] = fmaxf(s + b1[tid], 0.0f);
    __syncthreads();

    if (tid < 10) {
        float acc = b2[tid];
        const float* w = w2 + tid * 128;
#pragma unroll 8
        for (int k = 0; k < 128; k++)
            acc = fmaf(s_h[k], w[k], acc);
        out[b * 10 + tid] = acc;
    }
}

// ============================================================================
extern "C" void kernel_launch(void* const* d_in, const int* in_sizes, int n_in,
                              void* d_out, int out_size)
{
    const float* x   = (const float*)d_in[0];
    const float* c1w = (const float*)d_in[1];
    const float* c1b = (const float*)d_in[2];
    const float* c2w = (const float*)d_in[3];
    const float* c2b = (const float*)d_in[4];
    const float* f1w = (const float*)d_in[5];
    const float* f1b = (const float*)d_in[6];
    const float* f2w = (const float*)d_in[7];
    const float* f2b = (const float*)d_in[8];
    float* out       = (float*)d_out;

    // dynamic smem = max(staging 93584 B, epilogue 147456 B)
    const int smem = 64 * 576 * (int)sizeof(float);   // 147456
    cudaFuncSetAttribute(convs_fused,
                         cudaFuncAttributeMaxDynamicSharedMemorySize, smem);

    convs_fused<<<512, 512, smem>>>(x, c1w, c1b, c2w, c2b);

    dim3 g2(8, 16);
    fc1_tc<<<g2, 256>>>(f1w);

    fc_tail<<<512, 128>>>(f1b, f2w, f2b, out);
}

// round 9
// speedup vs baseline: 2.9280x; 1.1273x over previous
#include <cuda_runtime.h>
#include <cuda_fp16.h>
#include <cstdint>

// ---------------- scratch (device globals: allocation-free) ----------------
__device__ __half g_pool2h[512 * 9216];         // conv2 out, NCHW flat, fp16
__device__ __half g_fc1w_h[128 * 9216];         // fc1 weights, fp16
__device__ float  g_fc1part[32 * 512 * 128];    // fc1 split-K partials

__device__ __forceinline__ uint32_t smem_u32(const void* p) {
    return (uint32_t)__cvta_generic_to_shared(p);
}
__device__ __forceinline__ uint64_t pack2(float lo, float hi) {
    uint64_t r;
    asm("mov.b64 %0, {%1, %2};" : "=l"(r) : "f"(lo), "f"(hi));
    return r;
}
__device__ __forceinline__ void fma2(uint64_t& d, uint64_t a, uint64_t b) {
    asm("fma.rn.f32x2 %0, %1, %2, %0;" : "+l"(d) : "l"(a), "l"(b));
}
__device__ __forceinline__ void unpack2(uint64_t v, float& lo, float& hi) {
    uint32_t l, h;
    asm("mov.b64 {%0, %1}, %2;" : "=r"(l), "=r"(h) : "l"(v));
    lo = __uint_as_float(l);
    hi = __uint_as_float(h);
}
__device__ __forceinline__ uint32_t cvt_f16x2(float hi, float lo) {
    uint32_t r;
    asm("cvt.rn.f16x2.f32 %0, %1, %2;" : "=r"(r) : "f"(hi), "f"(lo));
    return r;
}

// fp16 tensor-core MMA, fp32 accum (baseline PTX, sm_80+).
__device__ __forceinline__ void mma_f16(float c[4],
                                        uint32_t a0, uint32_t a1,
                                        uint32_t a2, uint32_t a3,
                                        uint32_t b0, uint32_t b1) {
    asm volatile(
        "mma.sync.aligned.m16n8k16.row.col.f32.f16.f16.f32 "
        "{%0,%1,%2,%3}, {%4,%5,%6,%7}, {%8,%9}, {%0,%1,%2,%3};"
        : "+f"(c[0]), "+f"(c[1]), "+f"(c[2]), "+f"(c[3])
        : "r"(a0), "r"(a1), "r"(a2), "r"(a3), "r"(b0), "r"(b1));
}
__device__ __forceinline__ void ldmx4(uint32_t r[4], uint32_t addr) {
    asm volatile(
        "ldmatrix.sync.aligned.m8n8.x4.shared.b16 {%0,%1,%2,%3}, [%4];"
        : "=r"(r[0]), "=r"(r[1]), "=r"(r[2]), "=r"(r[3]) : "r"(addr));
}
__device__ __forceinline__ void ldmx2(uint32_t& r0, uint32_t& r1, uint32_t addr) {
    asm volatile(
        "ldmatrix.sync.aligned.m8n8.x2.shared.b16 {%0,%1}, [%2];"
        : "=r"(r0), "=r"(r1) : "r"(addr));
}

// ============================================================================
// K0: one-time fc1 weight fp32 -> fp16 (halves fc1's B traffic; B is re-read
// 8x so this pays for itself).  1179648 elems, float2 -> f16x2.
// ============================================================================
__global__ void __launch_bounds__(512) cvt_w1(const float* __restrict__ w)
{
    const int i = (blockIdx.x * 512 + threadIdx.x);
    const float2 v = *(const float2*)(w + i * 2);
    *(uint32_t*)(g_fc1w_h + i * 2) = cvt_f16x2(v.y, v.x);
}

// ============================================================================
// K1 (fused): conv1+relu+pool (f32x2 FMA) -> conv2 via fp16 m16n8k16 mma
//             -> bias+relu+pool -> NCHW fp16 gmem.
// One CTA = one image, 16 warps. All threads stage, then all threads conv1.
// conv2 GEMM: M = 640 pixel rows over the 26-grid, N = 64 oc,
// K = 9 shifts x 32 ic (2 k16-steps per shift).
// A/B smem: 64B rows; swizzle chunk c ^= (row>>1)&3 -> conflict-free LDSM.
// ============================================================================
__global__ void __launch_bounds__(512, 1) convs_fused(
    const float* __restrict__ x,
    const float* __restrict__ w1,
    const float* __restrict__ b1,
    const float* __restrict__ w2,
    const float* __restrict__ b2)
{
    extern __shared__ char smc[];
    __half* s_a   = (__half*)smc;                 // 704 rows x 64B = 45056 B
    __half* s_b   = (__half*)(smc + 45056);       // 9*64 rows x 64B = 36864 B
    float*  s_img = (float*)(smc + 81920);        // 54*54 f32 = 11664 B
    float*  s_epi = (float*)smc;                  // 64 x 576 f32 (reuse)
    __shared__ uint64_t s_w1d[32 * 9];            // conv1 weights (w,w)
    __shared__ float s_b1[32];
    __shared__ float s_bias[64];

    const int b    = blockIdx.x;
    const int tid  = threadIdx.x;
    const int wid  = tid >> 5;
    const int lane = tid & 31;
    const int g    = lane >> 2;
    const int tig  = lane & 3;
    const int mg   = wid & 7;       // m-group: 5 m16-tiles
    const int ng   = wid >> 3;      // n-half: 4 n8-tiles

    // ---- phase 0 (all threads): image + all weights + biases + pad ----
    {
        const float4* xb4 = (const float4*)(x + b * 54 * 54);
        float4* si4 = (float4*)s_img;
        for (int i = tid; i < 729; i += 512) si4[i] = xb4[i];
    }
    for (int i = tid; i < 32 * 9; i += 512) {
        const float wv = w1[i];
        s_w1d[i] = pack2(wv, wv);
    }
    if (tid < 32) s_b1[tid] = b1[tid];
    if (tid < 64) s_bias[tid] = b2[tid];
    // conv2 weights -> fp16 swizzled rows (coalesced gmem: i has s fastest)
    for (int i = tid; i < 64 * 32 * 9; i += 512) {
        const int n = i / 288;
        const int r = i % 288;
        const int k = r / 9;
        const int s = r % 9;
        const int row = s * 64 + n;
        *(__half*)((char*)s_b + row * 64 +
            ((((k >> 3) ^ ((n >> 1) & 3)) << 4) | ((k & 7) << 1))) =
            __float2half_rn(w2[i]);
    }
    for (int i = 676 * 16 + tid; i < 704 * 16; i += 512)
        ((uint32_t*)s_a)[i] = 0u;     // zero A rows 676..703
    __syncthreads();

    // ---- phase 1 (all 512 threads): conv1 + relu + pool -> fp16 s_a ----
    for (int m = tid; m < 676; m += 512) {
        const int ph = m / 26, pw = m % 26;
        float in[4][4];
#pragma unroll
        for (int r = 0; r < 4; r++)
#pragma unroll
            for (int c = 0; c < 4; c++)
                in[r][c] = s_img[(2 * ph + r) * 54 + 2 * pw + c];
        uint64_t ap[4][3];
#pragma unroll
        for (int r = 0; r < 4; r++)
#pragma unroll
            for (int j = 0; j < 3; j++)
                ap[r][j] = pack2(in[r][j], in[r][j + 1]);

        char* arow = (char*)s_a + m * 64;
        const int sw2 = (m >> 1) & 3;
#pragma unroll 2
        for (int oc2 = 0; oc2 < 16; oc2++) {
            const int oca = oc2 * 2, ocb = oca + 1;
            uint64_t va0 = 0ull, va1 = 0ull, vb0 = 0ull, vb1 = 0ull;
#pragma unroll
            for (int t = 0; t < 9; t++) {
                const uint64_t wa = s_w1d[oca * 9 + t];
                const uint64_t wb = s_w1d[ocb * 9 + t];
                fma2(va0, ap[t / 3][t % 3], wa);
                fma2(va1, ap[t / 3 + 1][t % 3], wa);
                fma2(vb0, ap[t / 3][t % 3], wb);
                fma2(vb1, ap[t / 3 + 1][t % 3], wb);
            }
            float a00, a01, a10, a11, b00, b01, b10, b11;
            unpack2(va0, a00, a01); unpack2(va1, a10, a11);
            unpack2(vb0, b00, b01); unpack2(vb1, b10, b11);
            float ma = fmaxf(fmaxf(a00, a01), fmaxf(a10, a11)) + s_b1[oca];
            float mb = fmaxf(fmaxf(b00, b01), fmaxf(b10, b11)) + s_b1[ocb];
            ma = fmaxf(ma, 0.0f);
            mb = fmaxf(mb, 0.0f);
            const uint32_t h2 = cvt_f16x2(mb, ma);
            *(uint32_t*)(arow +
                ((((oca >> 3) ^ sw2) << 4) | ((oca & 7) << 1))) = h2;
        }
    }
    __syncthreads();

    // ---- conv2 mainloop: 9 shifts x 2 k16-steps, fp16 MMA ----
    float acc[5][4][4];
#pragma unroll
    for (int i = 0; i < 5; i++)
#pragma unroll
        for (int n = 0; n < 4; n++)
#pragma unroll
            for (int q = 0; q < 4; q++) acc[i][n][q] = 0.0f;

    const int mbase = mg * 80;

    const uint32_t a_base = smem_u32(s_a);
    const uint32_t b_base = smem_u32(s_b);
    const int lrow15 = lane & 15;
    const int lhi    = lane >> 4;
    const int bch    = (lane >> 3) & 1;
    const int bsw    = ((lane & 7) >> 1) & 3;
    const uint32_t b_lane_base = b_base + (ng * 32 + (lane & 7)) * 64;

#pragma unroll 1
    for (int s = 0; s < 9; s++) {
        const int roff = (s / 3) * 26 + (s % 3);
        const int arow = mbase + roff + lrow15;
        const int asw  = (arow >> 1) & 3;
        const uint32_t a_row_addr = a_base + arow * 64;
        const uint32_t b_row_addr = b_lane_base + s * 4096;

#pragma unroll
        for (int ks = 0; ks < 2; ks++) {
            const uint32_t aaddr =
                a_row_addr + ((uint32_t)((((ks << 1) + lhi) ^ asw)) << 4);
            const uint32_t bk =
                b_row_addr + ((uint32_t)((((ks << 1) + bch) ^ bsw)) << 4);

            uint32_t a[5][4];
#pragma unroll
            for (int i = 0; i < 5; i++) ldmx4(a[i], aaddr + i * 1024);

#pragma unroll
            for (int nt = 0; nt < 4; nt++) {
                uint32_t b0, b1;
                ldmx2(b0, b1, bk + nt * 512);
#pragma unroll
                for (int i = 0; i < 5; i++)
                    mma_f16(acc[i][nt], a[i][0], a[i][1], a[i][2], a[i][3], b0, b1);
            }
        }
    }
    __syncthreads();   // results in regs; staging smem dead -> reuse as s_epi

    // ---- epilogue: scatter bias-added outputs to [oc][pix] smem ----
#pragma unroll
    for (int i = 0; i < 5; i++) {
        const int r0 = mbase + i * 16 + g;
        const int r1 = r0 + 8;
        const int h0 = r0 / 26, w0 = r0 % 26;
        const int h1 = r1 / 26, w1 = r1 % 26;
#pragma unroll
        for (int n = 0; n < 4; n++) {
            const int col0 = ng * 32 + n * 8 + tig * 2;
            if (h0 < 24 && w0 < 24) {
                const int pix = h0 * 24 + w0;
                s_epi[col0 * 576 + pix]       = acc[i][n][0] + s_bias[col0];
                s_epi[(col0 + 1) * 576 + pix] = acc[i][n][1] + s_bias[col0 + 1];
            }
            if (h1 < 24 && w1 < 24) {
                const int pix = h1 * 24 + w1;
                s_epi[col0 * 576 + pix]       = acc[i][n][2] + s_bias[col0];
                s_epi[(col0 + 1) * 576 + pix] = acc[i][n][3] + s_bias[col0 + 1];
            }
        }
    }
    __syncthreads();

    // ---- 2x2 maxpool + relu -> fp16 NCHW flat (coalesced) ----
    __half* outp = g_pool2h + b * 9216;
    for (int j = tid; j < 9216; j += 512) {
        const int oc = j / 144;
        const int p  = j % 144;
        const int ph = p / 12, pw = p % 12;
        const float* e = s_epi + oc * 576 + (2 * ph) * 24 + 2 * pw;
        const float v = fmaxf(fmaxf(e[0], e[1]), fmaxf(e[24], e[25]));
        outp[j] = __float2half_rn(fmaxf(v, 0.0f));
    }
}

// ============================================================================
// K2: fc1 split-K (32 ways) via fp16 m16n8k16.  C[512,128] = A[512,9216]*W^T.
// A = g_pool2h fp16; B = g_fc1w_h fp16.  grid (8 mt, 32 ks), K=288/chunk.
// ============================================================================
__global__ void __launch_bounds__(256) fc1_tc()
{
    __shared__ __half sA[64 * 32];     // 64B rows, swizzled
    __shared__ __half sB[128 * 32];    // 64B rows, swizzled

    const int mt   = blockIdx.x;    // 0..7
    const int ks   = blockIdx.y;    // 0..31
    const int tid  = threadIdx.x;
    const int wid  = tid >> 5;
    const int lane = tid & 31;
    const int m0   = mt * 64;
    const int k0   = ks * 288;
    const int mi   = wid & 3;       // m16-tile
    const int nh   = wid >> 2;      // n-half (64 cols)

    const int lrow15 = lane & 15;
    const int lhi    = lane >> 4;
    const int bch    = (lane >> 3) & 1;
    const int bsw    = ((lane & 7) >> 1) & 3;

    const uint32_t sA_base = smem_u32(sA);
    const uint32_t sB_base = smem_u32(sB);
    const int arow = mi * 16 + lrow15;
    const int asw  = (arow >> 1) & 3;
    const uint32_t a_row_addr = sA_base + arow * 64;
    const uint32_t b_row_addr = sB_base + (nh * 64 + (lane & 7)) * 64;

    float acc[8][4];
#pragma unroll
    for (int n = 0; n < 8; n++)
#pragma unroll
        for (int q = 0; q < 4; q++) acc[n][q] = 0.0f;

#pragma unroll 1
    for (int kk = 0; kk < 288; kk += 32) {
        __syncthreads();
        for (int i = tid; i < 64 * 16; i += 256) {
            const int m = i >> 4, k = (i & 15) * 2;
            const uint32_t v =
                *(const uint32_t*)(g_pool2h + (m0 + m) * 9216 + k0 + kk + k);
            *(uint32_t*)((char*)sA + m * 64 +
                ((((k >> 3) ^ ((m >> 1) & 3)) << 4) | ((k & 7) << 1))) = v;
        }
        for (int i = tid; i < 128 * 16; i += 256) {
            const int n = i >> 4, k = (i & 15) * 2;
            const uint32_t v =
                *(const uint32_t*)(g_fc1w_h + n * 9216 + k0 + kk + k);
            *(uint32_t*)((char*)sB + n * 64 +
                ((((k >> 3) ^ ((n >> 1) & 3)) << 4) | ((k & 7) << 1))) = v;
        }
        __syncthreads();

#pragma unroll
        for (int kstep = 0; kstep < 2; kstep++) {
            uint32_t a[4];
            ldmx4(a, a_row_addr +
                     ((uint32_t)((((kstep << 1) + lhi) ^ asw)) << 4));
            const uint32_t bk =
                b_row_addr + ((uint32_t)((((kstep << 1) + bch) ^ bsw)) << 4);
#pragma unroll
            for (int nt = 0; nt < 8; nt++) {
                uint32_t b0, b1;
                ldmx2(b0, b1, bk + nt * 512);
                mma_f16(acc[nt], a[0], a[1], a[2], a[3], b0, b1);
            }
        }
    }

    float* P = g_fc1part + (ks * 512 + m0) * 128;
    const int g   = lane >> 2;
    const int tig = lane & 3;
    const int r0  = mi * 16 + g;
#pragma unroll
    for (int n = 0; n < 8; n++) {
        const int c0 = nh * 64 + n * 8 + tig * 2;
        P[r0 * 128 + c0]           = acc[n][0];
        P[r0 * 128 + c0 + 1]       = acc[n][1];
        P[(r0 + 8) * 128 + c0]     = acc[n][2];
        P[(r0 + 8) * 128 + c0 + 1] = acc[n][3];
    }
}

// ============================================================================
// K3: reduce split-K partials + bias + relu + fc2 (128->10).
// ============================================================================
__global__ void __launch_bounds__(128) fc_tail(
    const float* __restrict__ b1,
    const float* __restrict__ w2,
    const float* __restrict__ b2,
    float* __restrict__ out)
{
    __shared__ float s_h[128];
    const int b   = blockIdx.x;
    const int tid = threadIdx.x;

    float s = 0.f;
#pragma unroll
    for (int ks = 0; ks < 32; ks++)
        s += g_fc1part[(ks * 512 + b) * 128 + tid];
    s_h[tid] = fmaxf(s + b1[tid], 0.0f);
    __syncthreads();

    if (tid < 10) {
        float acc = b2[tid];
        const float* w = w2 + tid * 128;
#pragma unroll 8
        for (int k = 0; k < 128; k++)
            acc = fmaf(s_h[k], w[k], acc);
        out[b * 10 + tid] = acc;
    }
}

// ============================================================================
extern "C" void kernel_launch(void* const* d_in, const int* in_sizes, int n_in,
                              void* d_out, int out_size)
{
    const float* x   = (const float*)d_in[0];
    const float* c1w = (const float*)d_in[1];
    const float* c1b = (const float*)d_in[2];
    const float* c2w = (const float*)d_in[3];
    const float* c2b = (const float*)d_in[4];
    const float* f1w = (const float*)d_in[5];
    const float* f1b = (const float*)d_in[6];
    const float* f2w = (const float*)d_in[7];
    const float* f2b = (const float*)d_in[8];
    float* out       = (float*)d_out;

    const int smem = 64 * 576 * (int)sizeof(float);   // 147456
    cudaFuncSetAttribute(convs_fused,
                         cudaFuncAttributeMaxDynamicSharedMemorySize, smem);

    cvt_w1<<<1152, 512>>>(f1w);                       // 128*9216/2/512
    convs_fused<<<512, 512, smem>>>(x, c1w, c1b, c2w, c2b);

    dim3 g2(8, 32);
    fc1_tc<<<g2, 256>>>();

    fc_tail<<<512, 128>>>(f1b, f2w, f2b, out);
}